// round 12
// baseline (speedup 1.0000x reference)
#include <cuda_runtime.h>
#include <math.h>
#include <stdint.h>

namespace {

constexpr int Bc = 8, Sc = 1024, Ec = 768, Hc = 12, Pc = 64, HPc = 768;
constexpr int TILEF = 8192;   // floats per 128x64 fragment-order tile

__device__ float g_k[Bc * Hc * Sc * Pc];     // raw (flash scales+rounds)
__device__ float g_v[Bc * Hc * Sc * Pc];     // rounded, row-major (qv GEMM B)
__device__ float g_qvf[Bc * Hc * Sc * Pc];   // rounded, FRAG-ORDER (flash K)
__device__ float g_vf[Bc * Hc * Sc * Pc];    // rounded, FRAG-ORDER (flash V)
__device__ float g_attn[Bc * Sc * HPc];      // rounded (lift A via cp.async)
__device__ float g_wkv[Hc * Ec * 128];       // rounded kp||vp
__device__ float g_lw[HPc * Ec];             // rounded lifting

__device__ __forceinline__ float to_tf32(float x) {
    float y;
    asm("cvt.rna.tf32.f32 %0, %1;" : "=f"(y) : "f"(x));
    return y;
}

__device__ __forceinline__ void mma_tf32(float c[4], const uint32_t a[4],
                                         const uint32_t b[2]) {
    asm volatile(
        "mma.sync.aligned.m16n8k8.row.col.f32.tf32.tf32.f32 "
        "{%0,%1,%2,%3}, {%4,%5,%6,%7}, {%8,%9}, {%0,%1,%2,%3};"
        : "+f"(c[0]), "+f"(c[1]), "+f"(c[2]), "+f"(c[3])
        : "r"(a[0]), "r"(a[1]), "r"(a[2]), "r"(a[3]), "r"(b[0]), "r"(b[1]));
}

__device__ __forceinline__ uint32_t smem_u32(const void* p) {
    uint32_t a;
    asm("{ .reg .u64 t; cvta.to.shared.u64 t, %1; cvt.u32.u64 %0, t; }"
        : "=r"(a) : "l"(p));
    return a;
}
__device__ __forceinline__ void cp_async16(uint32_t dst, const void* src) {
    asm volatile("cp.async.cg.shared.global [%0], [%1], 16;"
                 :: "r"(dst), "l"(src) : "memory");
}
#define CP_COMMIT() asm volatile("cp.async.commit_group;" ::: "memory")
#define CP_WAIT0()  asm volatile("cp.async.wait_group 0;" ::: "memory")

// within-tile float index of value K[jl][p] in the QK-B fragment-order tile
__device__ __forceinline__ int kf_index(int jl, int p) {
    int np = jl >> 4, r8 = (jl >> 3) & 1, qr = jl & 7;
    int k8 = p >> 3, q7 = p & 7, qk = q7 & 3, half = q7 >> 2;
    return (((k8 * 8 + np) * 32 + qr * 4 + qk) << 2) + r8 * 2 + half;
}
// within-tile float index of value V[jl][p] in the PV-B fragment-order tile
__device__ __forceinline__ int vf_index(int jl, int p) {
    int kk8 = jl >> 3, j7 = jl & 7, qk = j7 & 3, halfj = j7 >> 2;
    int np = p >> 4, r8 = (p >> 3) & 1, qr = p & 7;
    return (((kk8 * 4 + np) * 32 + qr * 4 + qk) << 2) + r8 * 2 + halfj;
}

// ---------------------------------------------------------------------------
// Prologue: RNA-round the weights into scratch.
// ---------------------------------------------------------------------------
constexpr int RW_N1 = Hc * Ec * 128 / 4;
constexpr int RW_N2 = HPc * Ec / 4;

__global__ __launch_bounds__(256)
void round_weights(const float* __restrict__ kp, const float* __restrict__ vp,
                   const float* __restrict__ lw) {
    int idx = blockIdx.x * 256 + threadIdx.x;
    if (idx < RW_N1) {
        int n4 = (idx & 31) * 4;
        int e = (idx >> 5) % Ec;
        int h = idx / (32 * Ec);
        float4 v = (n4 < 64)
            ? *(const float4*)(kp + ((size_t)h * Ec + e) * Pc + n4)
            : *(const float4*)(vp + ((size_t)h * Ec + e) * Pc + (n4 - 64));
        v.x = to_tf32(v.x); v.y = to_tf32(v.y);
        v.z = to_tf32(v.z); v.w = to_tf32(v.w);
        ((float4*)g_wkv)[idx] = v;
    } else if (idx < RW_N1 + RW_N2) {
        int f = idx - RW_N1;
        float4 v = ((const float4*)lw)[f];
        v.x = to_tf32(v.x); v.y = to_tf32(v.y);
        v.z = to_tf32(v.z); v.w = to_tf32(v.w);
        ((float4*)g_lw)[f] = v;
    }
}

// ---------------------------------------------------------------------------
// tf32 mma.sync GEMM, double-buffered, k-step 32.
// Frag-order outputs (g_qvf / g_vf) staged through smem -> coalesced STG.
// MODE 0: proj  MODE 1: qv (NT=64)  MODE 2: lift
// ---------------------------------------------------------------------------
constexpr int ACH = 33;
constexpr int AFL = 2 * 128 * 36;

template <int NT, int MODE>
__global__ __launch_bounds__(256, 2)
void mma_gemm(const float* __restrict__ P0, float* __restrict__ Out) {
    constexpr bool CPA = (MODE == 2);
    constexpr int WR = (NT == 128) ? 2 : 4;
    constexpr int WC = (NT == 128) ? 4 : 2;
    constexpr int WM = 128 / WR;
    constexpr int WN = NT / WC;
    constexpr int MT = WM / 16;
    constexpr int NTT = WN / 8;
    constexpr int BSTR = NT + 8;
    constexpr int NB4 = (32 * NT) / (4 * 256);

    extern __shared__ float smg[];
    float4* Ax = (float4*)smg;
    float (*Asp)[36] = (float(*)[36])smg;
    float (*Bs)[BSTR] = (float(*)[BSTR])(smg + AFL);
    const uint32_t as_base = smem_u32(smg);
    const uint32_t bs_base = smem_u32(smg + AFL);

    const int tid = threadIdx.x;
    const int wid = tid >> 5, lane = tid & 31;
    const int wr = (NT == 128) ? (wid >> 2) : (wid >> 1);
    const int wc = (NT == 128) ? (wid & 3) : (wid & 1);
    const int wm0 = wr * WM, wn0 = wc * WN;
    const int qk = lane & 3, qr = lane >> 2;
    const int mtile0 = wm0 >> 4;

    const int row0 = blockIdx.x * 128;
    const int hy = blockIdx.y, bz = blockIdx.z;

    const float* A;
    int lda, K;
    const float* Bg = nullptr;
    int ldb = 0;
    int n0g = 0;
    if (MODE == 0) {
        A = P0 + (size_t)bz * Sc * Ec; lda = Ec; K = Ec;
        Bg = g_wkv + (size_t)hy * Ec * 128; ldb = 128;
    } else if (MODE == 1) {
        A = P0 + (size_t)hy * Sc * Sc; lda = Sc; K = Sc;
        Bg = g_v + (size_t)(bz * Hc + hy) * Sc * Pc; ldb = Pc;
    } else {
        A = g_attn; lda = HPc; K = HPc;
        n0g = blockIdx.y * 128;
        Bg = g_lw + n0g; ldb = Ec;
    }

    float c[MT][NTT][4];
#pragma unroll
    for (int mt = 0; mt < MT; mt++)
#pragma unroll
        for (int nt = 0; nt < NTT; nt++)
#pragma unroll
            for (int q = 0; q < 4; q++) c[mt][nt][q] = 0.f;

    float4 pa[4];

    auto fillB = [&](int t) {
        const int k0 = t * 32, buf = t & 1;
#pragma unroll
        for (int j = 0; j < NB4; j++) {
            int i = j * 256 + tid;
            int kk = (NT == 128) ? (i >> 5) : (i >> 4);
            int n4 = (NT == 128) ? ((i & 31) * 4) : ((i & 15) * 4);
            cp_async16(bs_base + (uint32_t)(((buf * 32 + kk) * BSTR + n4) * 4),
                       Bg + (size_t)(k0 + kk) * ldb + n4);
        }
    };
    auto fillA_cp = [&](int t) {
        const int k0 = t * 32, buf = t & 1;
#pragma unroll
        for (int j = 0; j < 4; j++) {
            int i = j * 256 + tid;
            int m = i >> 3, e4 = (i & 7) * 4;
            cp_async16(as_base + (uint32_t)(((buf * 128 + m) * 36 + e4) * 4),
                       A + (size_t)(row0 + m) * lda + k0 + e4);
        }
    };
    auto loadA = [&](int k0) {
#pragma unroll
        for (int j = 0; j < 4; j++) {
            int i = j * 256 + tid;
            int m = i >> 3, e4 = (i & 7) * 4;
            pa[j] = *(const float4*)(A + (size_t)(row0 + m) * lda + k0 + e4);
        }
    };
    auto storeA = [&](int buf) {
#pragma unroll
        for (int j = 0; j < 4; j++) {
            int i = j * 256 + tid;
            int m = i >> 3, e4 = (i & 7) * 4;
            int mtile = m >> 4, k8 = e4 >> 3;
            int comp = ((m >> 3) & 1) | (((e4 >> 2) & 1) << 1);
            int lane0 = (m & 7) * 4;
            float* dst = smg + (((buf * 8 + mtile) * 4 + k8) * ACH + lane0) * 4 + comp;
            dst[0]  = to_tf32(pa[j].x);
            dst[4]  = to_tf32(pa[j].y);
            dst[8]  = to_tf32(pa[j].z);
            dst[12] = to_tf32(pa[j].w);
        }
    };

    fillB(0);
    if constexpr (CPA) fillA_cp(0);
    CP_COMMIT();
    if constexpr (!CPA) { loadA(0); storeA(0); }
    CP_WAIT0();
    __syncthreads();

    const int nT = K / 32;
    for (int t = 0; t < nT; t++) {
        if (t + 1 < nT) {
            fillB(t + 1);
            if constexpr (CPA) fillA_cp(t + 1);
            CP_COMMIT();
            if constexpr (!CPA) loadA((t + 1) * 32);
        }
        const int ab8 = (t & 1) * 8, ab = (t & 1) * 128, bb = (t & 1) * 32;
#pragma unroll
        for (int k8 = 0; k8 < 4; k8++) {
            const int kk8 = k8 * 8;
            uint32_t a[MT][4], b[NTT][2];
#pragma unroll
            for (int mt = 0; mt < MT; mt++) {
                if constexpr (CPA) {
                    int m0 = wm0 + mt * 16;
                    a[mt][0] = __float_as_uint(Asp[ab + m0 + qr][kk8 + qk]);
                    a[mt][1] = __float_as_uint(Asp[ab + m0 + qr + 8][kk8 + qk]);
                    a[mt][2] = __float_as_uint(Asp[ab + m0 + qr][kk8 + qk + 4]);
                    a[mt][3] = __float_as_uint(Asp[ab + m0 + qr + 8][kk8 + qk + 4]);
                } else {
                    float4 av = Ax[((ab8 + mtile0 + mt) * 4 + k8) * ACH + lane];
                    a[mt][0] = __float_as_uint(av.x);
                    a[mt][1] = __float_as_uint(av.y);
                    a[mt][2] = __float_as_uint(av.z);
                    a[mt][3] = __float_as_uint(av.w);
                }
            }
#pragma unroll
            for (int nt = 0; nt < NTT; nt++) {
                int n0 = wn0 + nt * 8;
                b[nt][0] = __float_as_uint(Bs[bb + kk8 + qk][n0 + qr]);
                b[nt][1] = __float_as_uint(Bs[bb + kk8 + qk + 4][n0 + qr]);
            }
#pragma unroll
            for (int mt = 0; mt < MT; mt++)
#pragma unroll
                for (int nt = 0; nt < NTT; nt++)
                    mma_tf32(c[mt][nt], a[mt], b[nt]);
        }
        if (t + 1 < nT) {
            if constexpr (!CPA) storeA((t + 1) & 1);
            CP_WAIT0();
        }
        __syncthreads();
    }

    // ---- epilogue ----
#pragma unroll
    for (int mt = 0; mt < MT; mt++) {
#pragma unroll
        for (int nt = 0; nt < NTT; nt++) {
            int rl = wm0 + mt * 16 + qr;          // local row in tile
            int row = row0 + rl;
            int col = wn0 + nt * 8 + 2 * qk;
            float2 lo = make_float2(c[mt][nt][0], c[mt][nt][1]);
            float2 hi = make_float2(c[mt][nt][2], c[mt][nt][3]);
            if (MODE == 0) {
                size_t off = (size_t)(bz * Hc + hy) * Sc * Pc;
                int cc = col & 63;
                if (col < 64) {   // g_k: raw (flash rounds after scaling)
                    *(float2*)(g_k + off + (size_t)row * Pc + cc) = lo;
                    *(float2*)(g_k + off + (size_t)(row + 8) * Pc + cc) = hi;
                } else {          // g_v rounded row-major + staged frag tile
                    lo.x = to_tf32(lo.x); lo.y = to_tf32(lo.y);
                    hi.x = to_tf32(hi.x); hi.y = to_tf32(hi.y);
                    *(float2*)(g_v + off + (size_t)row * Pc + cc) = lo;
                    *(float2*)(g_v + off + (size_t)(row + 8) * Pc + cc) = hi;
                    smg[vf_index(rl, cc)]         = lo.x;
                    smg[vf_index(rl, cc + 1)]     = lo.y;
                    smg[vf_index(rl + 8, cc)]     = hi.x;
                    smg[vf_index(rl + 8, cc + 1)] = hi.y;
                }
            } else if (MODE == 1) {   // staged frag tile only
                smg[kf_index(rl, col)]         = to_tf32(lo.x);
                smg[kf_index(rl, col + 1)]     = to_tf32(lo.y);
                smg[kf_index(rl + 8, col)]     = to_tf32(hi.x);
                smg[kf_index(rl + 8, col + 1)] = to_tf32(hi.y);
            } else {
                *(float2*)(Out + (size_t)row * Ec + n0g + col) = lo;
                *(float2*)(Out + (size_t)(row + 8) * Ec + n0g + col) = hi;
            }
        }
    }
    if (MODE == 0 || MODE == 1) {   // coalesced stream of the staged tile
        __syncthreads();
        float* dstg = (MODE == 0 ? g_vf : g_qvf) +
                      (((size_t)(bz * Hc + hy)) * 8 + blockIdx.x) * TILEF;
#pragma unroll
        for (int j = 0; j < 8; j++) {
            int i = (j * 256 + tid) * 4;
            *(float4*)(dstg + i) = *(const float4*)(smg + i);
        }
    }
}

constexpr int SMG128 = (AFL + 2 * 32 * 136) * (int)sizeof(float);
constexpr int SMG64  = (AFL + 2 * 32 * 72) * (int)sizeof(float);

// ---------------------------------------------------------------------------
// Flash attention, mma.sync tf32, fragment-order K/V, softmax/MMA pipelined
// in 64-col halves:  S_A,S_B -> softmax_A -> PV_A -> softmax_B -> PV_B.
// Smem: KF[2][8192], VF[2][8192], Ps[128][132].
// ---------------------------------------------------------------------------
constexpr int PSOFF = 4 * TILEF;
constexpr int SMEM_FLASH = (PSOFF + 128 * 132) * (int)sizeof(float);

__global__ __launch_bounds__(256, 1)
void flash_mma() {
    extern __shared__ float smf[];
    float (*Ps)[132] = (float(*)[132])(smf + PSOFF);
    const uint32_t ks_base = smem_u32(smf);
    const uint32_t vs_base = smem_u32(smf + 2 * TILEF);

    const int i0 = (gridDim.x - 1 - blockIdx.x) * 128;  // heavy blocks first
    const int h = blockIdx.y, b = blockIdx.z;
    const int tid = threadIdx.x;
    const int wid = tid >> 5, lane = tid & 31;
    const int qk = lane & 3, qr = lane >> 2;
    const int m0 = wid * 16;

    const int bh = b * Hc + h;
    const float* kb = g_k + (size_t)bh * Sc * Pc;
    const float* kfb = g_qvf + (size_t)bh * 8 * TILEF;
    const float* vfb = g_vf + (size_t)bh * 8 * TILEF;
    const float qscale = rsqrtf((float)Ec);

    // Q fragments in registers
    uint32_t qa[8][4];
    {
        const int r0g = i0 + m0 + qr, r1g = r0g + 8;
#pragma unroll
        for (int k8 = 0; k8 < 8; k8++) {
            int c0 = k8 * 8 + qk;
            qa[k8][0] = __float_as_uint(to_tf32(kb[(size_t)r0g * Pc + c0] * qscale));
            qa[k8][1] = __float_as_uint(to_tf32(kb[(size_t)r1g * Pc + c0] * qscale));
            qa[k8][2] = __float_as_uint(to_tf32(kb[(size_t)r0g * Pc + c0 + 4] * qscale));
            qa[k8][3] = __float_as_uint(to_tf32(kb[(size_t)r1g * Pc + c0 + 4] * qscale));
        }
    }

    auto fill = [&](int t) {
        const int buf = t & 1;
        const float* ksrc = kfb + (size_t)t * TILEF;
        const float* vsrc = vfb + (size_t)t * TILEF;
#pragma unroll
        for (int j = 0; j < 8; j++) {
            int i = (j * 256 + tid) * 4;
            cp_async16(ks_base + (uint32_t)((buf * TILEF + i) * 4), ksrc + i);
            cp_async16(vs_base + (uint32_t)((buf * TILEF + i) * 4), vsrc + i);
        }
        CP_COMMIT();
    };

    float mrow[2] = {-INFINITY, -INFINITY};
    float lrow[2] = {0.f, 0.f};
    float o[8][4];
#pragma unroll
    for (int nt = 0; nt < 8; nt++)
#pragma unroll
        for (int q = 0; q < 4; q++) o[nt][q] = 0.f;

    const int tN = i0 / 128 + 1;
    fill(0);

    for (int t = 0; t < tN; t++) {
        if (t + 1 < tN) fill(t + 1);
        if (t + 1 < tN)
            asm volatile("cp.async.wait_group 1;" ::: "memory");
        else
            asm volatile("cp.async.wait_group 0;" ::: "memory");
        __syncthreads();
        const float4* KF4 = (const float4*)smf + (t & 1) * (TILEF / 4);
        const float4* VF4 = (const float4*)(smf + 2 * TILEF) + (t & 1) * (TILEF / 4);

        // S = Q @ K^T (both halves)
        float s[16][4];
#pragma unroll
        for (int nt = 0; nt < 16; nt++)
#pragma unroll
            for (int q = 0; q < 4; q++) s[nt][q] = 0.f;

#pragma unroll
        for (int k8 = 0; k8 < 8; k8++) {
            const int base = k8 * 256 + lane;
#pragma unroll
            for (int np = 0; np < 8; np++) {
                float4 bb = KF4[base + np * 32];
                uint32_t b01[2] = {__float_as_uint(bb.x), __float_as_uint(bb.y)};
                uint32_t b23[2] = {__float_as_uint(bb.z), __float_as_uint(bb.w)};
                mma_tf32(s[2 * np], qa[k8], b01);
                mma_tf32(s[2 * np + 1], qa[k8], b23);
            }
        }

        if (t == tN - 1) {  // diagonal block: causal mask
            int r0 = m0 + qr, r1 = r0 + 8;
#pragma unroll
            for (int nt = 0; nt < 16; nt++) {
                int c0 = nt * 8 + 2 * qk;
                if (c0 > r0)     s[nt][0] = -INFINITY;
                if (c0 + 1 > r0) s[nt][1] = -INFINITY;
                if (c0 > r1)     s[nt][2] = -INFINITY;
                if (c0 + 1 > r1) s[nt][3] = -INFINITY;
            }
        }

        // per-half online softmax + PV, interleaved so softmax overlaps MMA
#pragma unroll
        for (int hf = 0; hf < 2; hf++) {
            const int ntb = hf * 8;
            float mx0 = mrow[0], mx1 = mrow[1];
#pragma unroll
            for (int nt = 0; nt < 8; nt++) {
                mx0 = fmaxf(mx0, fmaxf(s[ntb + nt][0], s[ntb + nt][1]));
                mx1 = fmaxf(mx1, fmaxf(s[ntb + nt][2], s[ntb + nt][3]));
            }
#pragma unroll
            for (int off = 1; off <= 2; off <<= 1) {
                mx0 = fmaxf(mx0, __shfl_xor_sync(0xffffffffu, mx0, off));
                mx1 = fmaxf(mx1, __shfl_xor_sync(0xffffffffu, mx1, off));
            }
            float alpha0 = __expf(mrow[0] - mx0);
            float alpha1 = __expf(mrow[1] - mx1);
            mrow[0] = mx0; mrow[1] = mx1;
            float sum0 = 0.f, sum1 = 0.f;
#pragma unroll
            for (int nt = 0; nt < 8; nt++) {
                int c0 = (ntb + nt) * 8 + 2 * qk;
                float p0 = to_tf32(__expf(s[ntb + nt][0] - mx0));
                float p1 = to_tf32(__expf(s[ntb + nt][1] - mx0));
                float p2 = to_tf32(__expf(s[ntb + nt][2] - mx1));
                float p3 = to_tf32(__expf(s[ntb + nt][3] - mx1));
                sum0 += p0 + p1;
                sum1 += p2 + p3;
                *(float2*)&Ps[m0 + qr][c0]     = make_float2(p0, p1);
                *(float2*)&Ps[m0 + qr + 8][c0] = make_float2(p2, p3);
            }
#pragma unroll
            for (int off = 1; off <= 2; off <<= 1) {
                sum0 += __shfl_xor_sync(0xffffffffu, sum0, off);
                sum1 += __shfl_xor_sync(0xffffffffu, sum1, off);
            }
            lrow[0] = lrow[0] * alpha0 + sum0;
            lrow[1] = lrow[1] * alpha1 + sum1;
#pragma unroll
            for (int nt = 0; nt < 8; nt++) {
                o[nt][0] *= alpha0; o[nt][1] *= alpha0;
                o[nt][2] *= alpha1; o[nt][3] *= alpha1;
            }
            __syncwarp();  // Ps rows are warp-private

            // PV for this half: kk8 in [8*hf, 8*hf+8)
#pragma unroll
            for (int kk8 = 0; kk8 < 8; kk8++) {
                const int kg = ntb + kk8;
                const int kc = kg * 8;
                uint32_t a[4];
                a[0] = __float_as_uint(Ps[m0 + qr][kc + qk]);
                a[1] = __float_as_uint(Ps[m0 + qr + 8][kc + qk]);
                a[2] = __float_as_uint(Ps[m0 + qr][kc + qk + 4]);
                a[3] = __float_as_uint(Ps[m0 + qr + 8][kc + qk + 4]);
#pragma unroll
                for (int np = 0; np < 4; np++) {
                    float4 bb = VF4[(kg * 4 + np) * 32 + lane];
                    uint32_t b01[2] = {__float_as_uint(bb.x), __float_as_uint(bb.y)};
                    uint32_t b23[2] = {__float_as_uint(bb.z), __float_as_uint(bb.w)};
                    mma_tf32(o[2 * np], a, b01);
                    mma_tf32(o[2 * np + 1], a, b23);
                }
            }
        }
        __syncthreads();  // all warps done with buf before it is refilled
    }

    float inv0 = 1.f / lrow[0], inv1 = 1.f / lrow[1];
    int r0 = i0 + m0 + qr, r1 = r0 + 8;
    float* d0 = g_attn + ((size_t)b * Sc + r0) * HPc + h * Pc;
    float* d1 = g_attn + ((size_t)b * Sc + r1) * HPc + h * Pc;
#pragma unroll
    for (int nt = 0; nt < 8; nt++) {
        int cc = nt * 8 + 2 * qk;
        *(float2*)(d0 + cc) = make_float2(to_tf32(o[nt][0] * inv0),
                                          to_tf32(o[nt][1] * inv0));
        *(float2*)(d1 + cc) = make_float2(to_tf32(o[nt][2] * inv1),
                                          to_tf32(o[nt][3] * inv1));
    }
}

}  // namespace

extern "C" void kernel_launch(void* const* d_in, const int* in_sizes, int n_in,
                              void* d_out, int out_size) {
    (void)in_sizes; (void)n_in; (void)out_size;
    const float* x  = (const float*)d_in[0];   // (B,1,S,E)
    const float* kp = (const float*)d_in[1];   // (H,E,P)
    const float* vp = (const float*)d_in[2];   // (H,E,P)
    const float* qh = (const float*)d_in[3];   // (H,S,S)
    const float* lw = (const float*)d_in[4];   // (1,HP,E)
    float* out = (float*)d_out;                // (B,S,E)

    cudaFuncSetAttribute(mma_gemm<128, 0>,
                         cudaFuncAttributeMaxDynamicSharedMemorySize, SMG128);
    cudaFuncSetAttribute(mma_gemm<64, 1>,
                         cudaFuncAttributeMaxDynamicSharedMemorySize, SMG64);
    cudaFuncSetAttribute(mma_gemm<128, 2>,
                         cudaFuncAttributeMaxDynamicSharedMemorySize, SMG128);
    cudaFuncSetAttribute(flash_mma,
                         cudaFuncAttributeMaxDynamicSharedMemorySize, SMEM_FLASH);

    round_weights<<<(RW_N1 + RW_N2 + 255) / 256, 256>>>(kp, vp, lw);
    mma_gemm<128, 0><<<dim3(Sc / 128, Hc, Bc), 256, SMG128>>>(x, nullptr);
    mma_gemm<64, 1><<<dim3(Sc / 128, Hc, Bc), 256, SMG64>>>(qh, nullptr);
    flash_mma<<<dim3(Sc / 128, Hc, Bc), 256, SMEM_FLASH>>>();
    mma_gemm<128, 2><<<dim3(Bc * Sc / 128, Ec / 128), 256, SMG128>>>(nullptr, out);
}

// round 13
// speedup vs baseline: 1.0705x; 1.0705x over previous
#include <cuda_runtime.h>
#include <math.h>
#include <stdint.h>

namespace {

constexpr int Bc = 8, Sc = 1024, Ec = 768, Hc = 12, Pc = 64, HPc = 768;
constexpr int TILEF = 8192;   // floats per 128x64 flash frag tile

__device__ float g_k[Bc * Hc * Sc * Pc];        // raw (flash scales+rounds)
__device__ float g_qvf[Bc * Hc * Sc * Pc];      // flash K, frag-order
__device__ float g_vf[Bc * Hc * Sc * Pc];       // flash V, frag-order
__device__ float g_vbf[Bc * Hc * Sc * Pc];      // qv GEMM B, B-frag tiles (32x64)
__device__ float g_attnf[Bc * Sc * HPc];        // lift A, A-frag tiles (128x32)
__device__ float g_wkvf[Hc * Ec * 128];         // proj B, B-frag tiles (32x128)
__device__ float g_lwf[HPc * Ec];               // lift B, B-frag tiles (32x128)

__device__ __forceinline__ float to_tf32(float x) {
    float y;
    asm("cvt.rna.tf32.f32 %0, %1;" : "=f"(y) : "f"(x));
    return y;
}

__device__ __forceinline__ void mma_tf32(float c[4], const uint32_t a[4],
                                         const uint32_t b[2]) {
    asm volatile(
        "mma.sync.aligned.m16n8k8.row.col.f32.tf32.tf32.f32 "
        "{%0,%1,%2,%3}, {%4,%5,%6,%7}, {%8,%9}, {%0,%1,%2,%3};"
        : "+f"(c[0]), "+f"(c[1]), "+f"(c[2]), "+f"(c[3])
        : "r"(a[0]), "r"(a[1]), "r"(a[2]), "r"(a[3]), "r"(b[0]), "r"(b[1]));
}

__device__ __forceinline__ uint32_t smem_u32(const void* p) {
    uint32_t a;
    asm("{ .reg .u64 t; cvta.to.shared.u64 t, %1; cvt.u32.u64 %0, t; }"
        : "=r"(a) : "l"(p));
    return a;
}
__device__ __forceinline__ void cp_async16(uint32_t dst, const void* src) {
    asm volatile("cp.async.cg.shared.global [%0], [%1], 16;"
                 :: "r"(dst), "l"(src) : "memory");
}
#define CP_COMMIT() asm volatile("cp.async.commit_group;" ::: "memory")
#define CP_WAIT0()  asm volatile("cp.async.wait_group 0;" ::: "memory")

// B-fragment tile layout (32 k x NT n): float4 chunk (k8, npair) at lane
// qr*4+qk holds {frag 2npair e0,e1, frag 2npair+1 e0,e1}.
__device__ __forceinline__ int bf_index(int kk, int n, int NT) {
    int k8 = kk >> 3, qk = kk & 3, e = (kk & 7) >> 2;
    int nf = n >> 3, qr = n & 7, npair = nf >> 1, f = nf & 1;
    return (((k8 * (NT / 16) + npair) * 32 + qr * 4 + qk) << 2) + f * 2 + e;
}
// A-fragment tile layout (128 m x 32 k): float4 chunk (mtile, k8) at lane
// holds {a0,a1,a2,a3} = {e0r0, e0r1, e1r0, e1r1}.
__device__ __forceinline__ int af_index(int m, int kk) {
    int mtile = m >> 4, r8 = (m >> 3) & 1, qr = m & 7;
    int k8 = kk >> 3, qk = kk & 3, e = (kk & 7) >> 2;
    return (((mtile * 4 + k8) * 32 + qr * 4 + qk) << 2) + e * 2 + r8;
}
// flash K tile (128 j x 64 p), QK-B frag order
__device__ __forceinline__ int kf_index(int jl, int p) {
    int np = jl >> 4, r8 = (jl >> 3) & 1, qr = jl & 7;
    int k8 = p >> 3, q7 = p & 7, qk = q7 & 3, half = q7 >> 2;
    return (((k8 * 8 + np) * 32 + qr * 4 + qk) << 2) + r8 * 2 + half;
}
// flash V tile (128 j x 64 p), PV-B frag order
__device__ __forceinline__ int vf_index(int jl, int p) {
    int kk8 = jl >> 3, j7 = jl & 7, qk = j7 & 3, halfj = j7 >> 2;
    int np = p >> 4, r8 = (p >> 3) & 1, qr = p & 7;
    return (((kk8 * 4 + np) * 32 + qr * 4 + qk) << 2) + r8 * 2 + halfj;
}

// ---------------------------------------------------------------------------
// Prologue: RNA-round weights into B-frag-order tiles.
// grid (24, 18): y<12 -> g_wkvf tile (h=y, t=x); y>=12 -> g_lwf (n0b=y-12, t=x)
// ---------------------------------------------------------------------------
__global__ __launch_bounds__(256)
void round_weights(const float* __restrict__ kp, const float* __restrict__ vp,
                   const float* __restrict__ lw) {
    __shared__ float sms[4096];
    const int t = blockIdx.x, y = blockIdx.y, tid = threadIdx.x;
    if (y < Hc) {
        const int h = y;
#pragma unroll
        for (int j = 0; j < 16; j++) {
            int i = j * 256 + tid;
            int kk = i >> 7, n = i & 127;
            int e = t * 32 + kk;
            float val = (n < 64) ? kp[((size_t)h * Ec + e) * Pc + n]
                                 : vp[((size_t)h * Ec + e) * Pc + (n - 64)];
            sms[bf_index(kk, n, 128)] = to_tf32(val);
        }
        __syncthreads();
        float* dst = g_wkvf + ((size_t)h * 24 + t) * 4096;
#pragma unroll
        for (int j = 0; j < 4; j++) {
            int i = (j * 256 + tid) * 4;
            *(float4*)(dst + i) = *(const float4*)(sms + i);
        }
    } else {
        const int n0b = y - Hc;
#pragma unroll
        for (int j = 0; j < 16; j++) {
            int i = j * 256 + tid;
            int kk = i >> 7, n = i & 127;
            float val = lw[(size_t)(t * 32 + kk) * Ec + n0b * 128 + n];
            sms[bf_index(kk, n, 128)] = to_tf32(val);
        }
        __syncthreads();
        float* dst = g_lwf + ((size_t)n0b * 24 + t) * 4096;
#pragma unroll
        for (int j = 0; j < 4; j++) {
            int i = (j * 256 + tid) * 4;
            *(float4*)(dst + i) = *(const float4*)(sms + i);
        }
    }
}

// ---------------------------------------------------------------------------
// tf32 mma.sync GEMM, double-buffered, k-step 32, ALL frag-order operands.
// MODE 0: proj  MODE 1: qv (NT=64)  MODE 2: lift (A via cp.async frag tiles)
// ---------------------------------------------------------------------------
constexpr int ACH = 33;
constexpr int AFL = 2 * 128 * 36;   // A region floats (covers both layouts)

template <int NT, int MODE>
__global__ __launch_bounds__(256, 2)
void mma_gemm(const float* __restrict__ P0, float* __restrict__ Out) {
    constexpr bool CPA = (MODE == 2);
    constexpr int WR = (NT == 128) ? 2 : 4;
    constexpr int WC = (NT == 128) ? 4 : 2;
    constexpr int WM = 128 / WR;
    constexpr int WN = NT / WC;
    constexpr int MT = WM / 16;
    constexpr int NTT = WN / 8;
    constexpr int TBf = 32 * NT;        // B tile floats (4096 / 2048)
    constexpr int TB4 = TBf / 4;

    extern __shared__ float smg[];
    float4* Ax = (float4*)smg;                   // MODE0/1 frag A (reg-staged)
    float4* AS4 = (float4*)smg;                  // MODE2 cp A tiles
    float4* BS4 = (float4*)(smg + AFL);
    const uint32_t as_base = smem_u32(smg);
    const uint32_t bs_base = smem_u32(smg + AFL);

    const int tid = threadIdx.x;
    const int wid = tid >> 5, lane = tid & 31;
    const int wr = (NT == 128) ? (wid >> 2) : (wid >> 1);
    const int wc = (NT == 128) ? (wid & 3) : (wid & 1);
    const int wm0 = wr * WM, wn0 = wc * WN;
    const int qk = lane & 3, qr = lane >> 2;
    const int mtile0 = wm0 >> 4;

    const int row0 = blockIdx.x * 128;
    const int hy = blockIdx.y, bz = blockIdx.z;

    const float* A = nullptr;
    int lda = 0, K;
    const float* Bgf = nullptr;
    const float* Agf = nullptr;
    int n0g = 0;
    if (MODE == 0) {
        A = P0 + (size_t)bz * Sc * Ec; lda = Ec; K = Ec;
        Bgf = g_wkvf + (size_t)hy * 24 * 4096;
    } else if (MODE == 1) {
        A = P0 + (size_t)hy * Sc * Sc; lda = Sc; K = Sc;
        Bgf = g_vbf + (size_t)(bz * Hc + hy) * 32 * 2048;
    } else {
        K = HPc;
        n0g = blockIdx.y * 128;
        Agf = g_attnf + (size_t)blockIdx.x * 24 * 4096;
        Bgf = g_lwf + (size_t)blockIdx.y * 24 * 4096;
    }

    float c[MT][NTT][4];
#pragma unroll
    for (int mt = 0; mt < MT; mt++)
#pragma unroll
        for (int nt = 0; nt < NTT; nt++)
#pragma unroll
            for (int q = 0; q < 4; q++) c[mt][nt][q] = 0.f;

    float4 pa[4];

    auto fillB = [&](int t) {
        const int buf = t & 1;
        const float* src = Bgf + (size_t)t * TBf;
#pragma unroll
        for (int j = 0; j < TB4 / 256; j++) {
            int i = j * 256 + tid;
            cp_async16(bs_base + (uint32_t)((buf * TB4 + i) * 16), src + i * 4);
        }
    };
    auto fillA_cp = [&](int t) {   // MODE 2: A-frag tile
        const int buf = t & 1;
        const float* src = Agf + (size_t)t * 4096;
#pragma unroll
        for (int j = 0; j < 4; j++) {
            int i = j * 256 + tid;
            cp_async16(as_base + (uint32_t)((buf * 1024 + i) * 16), src + i * 4);
        }
    };
    auto loadA = [&](int k0) {     // MODE 0/1: raw gmem
#pragma unroll
        for (int j = 0; j < 4; j++) {
            int i = j * 256 + tid;
            int m = i >> 3, e4 = (i & 7) * 4;
            pa[j] = *(const float4*)(A + (size_t)(row0 + m) * lda + k0 + e4);
        }
    };
    auto storeA = [&](int buf) {   // MODE 0/1: frag-order + RNA
#pragma unroll
        for (int j = 0; j < 4; j++) {
            int i = j * 256 + tid;
            int m = i >> 3, e4 = (i & 7) * 4;
            int mtile = m >> 4, k8 = e4 >> 3;
            int comp = ((m >> 3) & 1) | (((e4 >> 2) & 1) << 1);
            int lane0 = (m & 7) * 4;
            float* dst = smg + (((buf * 8 + mtile) * 4 + k8) * ACH + lane0) * 4 + comp;
            dst[0]  = to_tf32(pa[j].x);
            dst[4]  = to_tf32(pa[j].y);
            dst[8]  = to_tf32(pa[j].z);
            dst[12] = to_tf32(pa[j].w);
        }
    };

    fillB(0);
    if constexpr (CPA) fillA_cp(0);
    CP_COMMIT();
    if constexpr (!CPA) { loadA(0); storeA(0); }
    CP_WAIT0();
    __syncthreads();

    const int nT = K / 32;
    for (int t = 0; t < nT; t++) {
        if (t + 1 < nT) {
            fillB(t + 1);
            if constexpr (CPA) fillA_cp(t + 1);
            CP_COMMIT();
            if constexpr (!CPA) loadA((t + 1) * 32);
        }
        const int ab8 = (t & 1) * 8;
        const int abuf = (t & 1) * 1024, bbuf = (t & 1) * TB4;
#pragma unroll
        for (int k8 = 0; k8 < 4; k8++) {
            uint32_t a[MT][4], b[NTT][2];
#pragma unroll
            for (int mt = 0; mt < MT; mt++) {
                float4 av;
                if constexpr (CPA)
                    av = AS4[abuf + ((mtile0 + mt) * 4 + k8) * 32 + lane];
                else
                    av = Ax[((ab8 + mtile0 + mt) * 4 + k8) * ACH + lane];
                a[mt][0] = __float_as_uint(av.x);
                a[mt][1] = __float_as_uint(av.y);
                a[mt][2] = __float_as_uint(av.z);
                a[mt][3] = __float_as_uint(av.w);
            }
#pragma unroll
            for (int j = 0; j < NTT / 2; j++) {
                float4 bb = BS4[bbuf + (k8 * (NT / 16) + wc * 2 + j) * 32 + lane];
                b[2 * j][0]     = __float_as_uint(bb.x);
                b[2 * j][1]     = __float_as_uint(bb.y);
                b[2 * j + 1][0] = __float_as_uint(bb.z);
                b[2 * j + 1][1] = __float_as_uint(bb.w);
            }
#pragma unroll
            for (int mt = 0; mt < MT; mt++)
#pragma unroll
                for (int nt = 0; nt < NTT; nt++)
                    mma_tf32(c[mt][nt], a[mt], b[nt]);
        }
        if (t + 1 < nT) {
            if constexpr (!CPA) storeA((t + 1) & 1);
            CP_WAIT0();
        }
        __syncthreads();
    }

    // ---- epilogue ----
    const int bh = bz * Hc + hy;
#pragma unroll
    for (int mt = 0; mt < MT; mt++) {
#pragma unroll
        for (int nt = 0; nt < NTT; nt++) {
            int rl = wm0 + mt * 16 + qr;
            int row = row0 + rl;
            int col = wn0 + nt * 8 + 2 * qk;
            float2 lo = make_float2(c[mt][nt][0], c[mt][nt][1]);
            float2 hi = make_float2(c[mt][nt][2], c[mt][nt][3]);
            if (MODE == 0) {
                if (col < 64) {   // g_k raw
                    size_t off = (size_t)bh * Sc * Pc;
                    *(float2*)(g_k + off + (size_t)row * Pc + col) = lo;
                    *(float2*)(g_k + off + (size_t)(row + 8) * Pc + col) = hi;
                } else {          // stage flash-V frag + qv-B frag
                    int cc = col & 63;
                    lo.x = to_tf32(lo.x); lo.y = to_tf32(lo.y);
                    hi.x = to_tf32(hi.x); hi.y = to_tf32(hi.y);
                    smg[vf_index(rl, cc)]         = lo.x;
                    smg[vf_index(rl, cc + 1)]     = lo.y;
                    smg[vf_index(rl + 8, cc)]     = hi.x;
                    smg[vf_index(rl + 8, cc + 1)] = hi.y;
                    int tb = 8192 + (rl >> 5) * 2048;
                    smg[tb + bf_index(rl & 31, cc, 64)]           = lo.x;
                    smg[tb + bf_index(rl & 31, cc + 1, 64)]       = lo.y;
                    smg[tb + bf_index((rl + 8) & 31, cc, 64)]     = hi.x;
                    smg[tb + bf_index((rl + 8) & 31, cc + 1, 64)] = hi.y;
                }
            } else if (MODE == 1) {   // stage flash-K frag
                smg[kf_index(rl, col)]         = to_tf32(lo.x);
                smg[kf_index(rl, col + 1)]     = to_tf32(lo.y);
                smg[kf_index(rl + 8, col)]     = to_tf32(hi.x);
                smg[kf_index(rl + 8, col + 1)] = to_tf32(hi.y);
            } else {
                *(float2*)(Out + (size_t)row * Ec + n0g + col) = lo;
                *(float2*)(Out + (size_t)(row + 8) * Ec + n0g + col) = hi;
            }
        }
    }
    if (MODE == 0) {
        __syncthreads();
        float* d1 = g_vf + ((size_t)bh * 8 + blockIdx.x) * TILEF;
        float* d2 = g_vbf + ((size_t)bh * 32 + blockIdx.x * 4) * 2048;
#pragma unroll
        for (int j = 0; j < 8; j++) {
            int i = (j * 256 + tid) * 4;
            *(float4*)(d1 + i) = *(const float4*)(smg + i);
            *(float4*)(d2 + i) = *(const float4*)(smg + 8192 + i);
        }
    } else if (MODE == 1) {
        __syncthreads();
        float* d1 = g_qvf + ((size_t)bh * 8 + blockIdx.x) * TILEF;
#pragma unroll
        for (int j = 0; j < 8; j++) {
            int i = (j * 256 + tid) * 4;
            *(float4*)(d1 + i) = *(const float4*)(smg + i);
        }
    }
}

constexpr int SMG128 = (AFL + 2 * 4096) * (int)sizeof(float);
constexpr int SMG64  = (AFL + 2 * 2048) * (int)sizeof(float);

// ---------------------------------------------------------------------------
// Flash attention (R11 body), frag-order K/V; epilogue stages A-frag g_attnf.
// Smem: KF[2][8192], VF[2][8192], Ps[128][132].
// ---------------------------------------------------------------------------
constexpr int PSOFF = 4 * TILEF;
constexpr int SMEM_FLASH = (PSOFF + 128 * 132) * (int)sizeof(float);

__global__ __launch_bounds__(256, 1)
void flash_mma() {
    extern __shared__ float smf[];
    float (*Ps)[132] = (float(*)[132])(smf + PSOFF);
    const uint32_t ks_base = smem_u32(smf);
    const uint32_t vs_base = smem_u32(smf + 2 * TILEF);

    const int i0 = (gridDim.x - 1 - blockIdx.x) * 128;  // heavy blocks first
    const int h = blockIdx.y, b = blockIdx.z;
    const int tid = threadIdx.x;
    const int wid = tid >> 5, lane = tid & 31;
    const int qk = lane & 3, qr = lane >> 2;
    const int m0 = wid * 16;

    const int bh = b * Hc + h;
    const float* kb = g_k + (size_t)bh * Sc * Pc;
    const float* kfb = g_qvf + (size_t)bh * 8 * TILEF;
    const float* vfb = g_vf + (size_t)bh * 8 * TILEF;
    const float qscale = rsqrtf((float)Ec);

    // Q fragments in registers
    uint32_t qa[8][4];
    {
        const int r0g = i0 + m0 + qr, r1g = r0g + 8;
#pragma unroll
        for (int k8 = 0; k8 < 8; k8++) {
            int c0 = k8 * 8 + qk;
            qa[k8][0] = __float_as_uint(to_tf32(kb[(size_t)r0g * Pc + c0] * qscale));
            qa[k8][1] = __float_as_uint(to_tf32(kb[(size_t)r1g * Pc + c0] * qscale));
            qa[k8][2] = __float_as_uint(to_tf32(kb[(size_t)r0g * Pc + c0 + 4] * qscale));
            qa[k8][3] = __float_as_uint(to_tf32(kb[(size_t)r1g * Pc + c0 + 4] * qscale));
        }
    }

    auto fill = [&](int t) {
        const int buf = t & 1;
        const float* ksrc = kfb + (size_t)t * TILEF;
        const float* vsrc = vfb + (size_t)t * TILEF;
#pragma unroll
        for (int j = 0; j < 8; j++) {
            int i = (j * 256 + tid) * 4;
            cp_async16(ks_base + (uint32_t)((buf * TILEF + i) * 4), ksrc + i);
            cp_async16(vs_base + (uint32_t)((buf * TILEF + i) * 4), vsrc + i);
        }
        CP_COMMIT();
    };

    float mrow[2] = {-INFINITY, -INFINITY};
    float lrow[2] = {0.f, 0.f};
    float o[8][4];
#pragma unroll
    for (int nt = 0; nt < 8; nt++)
#pragma unroll
        for (int q = 0; q < 4; q++) o[nt][q] = 0.f;

    const int tN = i0 / 128 + 1;
    fill(0);

    for (int t = 0; t < tN; t++) {
        if (t + 1 < tN) fill(t + 1);
        if (t + 1 < tN)
            asm volatile("cp.async.wait_group 1;" ::: "memory");
        else
            asm volatile("cp.async.wait_group 0;" ::: "memory");
        __syncthreads();
        const float4* KF4 = (const float4*)smf + (t & 1) * (TILEF / 4);
        const float4* VF4 = (const float4*)(smf + 2 * TILEF) + (t & 1) * (TILEF / 4);

        float s[16][4];
#pragma unroll
        for (int nt = 0; nt < 16; nt++)
#pragma unroll
            for (int q = 0; q < 4; q++) s[nt][q] = 0.f;

#pragma unroll
        for (int k8 = 0; k8 < 8; k8++) {
            const int base = k8 * 256 + lane;
#pragma unroll
            for (int np = 0; np < 8; np++) {
                float4 bb = KF4[base + np * 32];
                uint32_t b01[2] = {__float_as_uint(bb.x), __float_as_uint(bb.y)};
                uint32_t b23[2] = {__float_as_uint(bb.z), __float_as_uint(bb.w)};
                mma_tf32(s[2 * np], qa[k8], b01);
                mma_tf32(s[2 * np + 1], qa[k8], b23);
            }
        }

        if (t == tN - 1) {  // diagonal block: causal mask
            int r0 = m0 + qr, r1 = r0 + 8;
#pragma unroll
            for (int nt = 0; nt < 16; nt++) {
                int c0 = nt * 8 + 2 * qk;
                if (c0 > r0)     s[nt][0] = -INFINITY;
                if (c0 + 1 > r0) s[nt][1] = -INFINITY;
                if (c0 > r1)     s[nt][2] = -INFINITY;
                if (c0 + 1 > r1) s[nt][3] = -INFINITY;
            }
        }

        float mx0 = mrow[0], mx1 = mrow[1];
#pragma unroll
        for (int nt = 0; nt < 16; nt++) {
            mx0 = fmaxf(mx0, fmaxf(s[nt][0], s[nt][1]));
            mx1 = fmaxf(mx1, fmaxf(s[nt][2], s[nt][3]));
        }
#pragma unroll
        for (int off = 1; off <= 2; off <<= 1) {
            mx0 = fmaxf(mx0, __shfl_xor_sync(0xffffffffu, mx0, off));
            mx1 = fmaxf(mx1, __shfl_xor_sync(0xffffffffu, mx1, off));
        }
        float alpha0 = __expf(mrow[0] - mx0);
        float alpha1 = __expf(mrow[1] - mx1);
        mrow[0] = mx0; mrow[1] = mx1;
        float sum0 = 0.f, sum1 = 0.f;
#pragma unroll
        for (int nt = 0; nt < 16; nt++) {
            int c0 = nt * 8 + 2 * qk;
            float p0 = to_tf32(__expf(s[nt][0] - mx0));
            float p1 = to_tf32(__expf(s[nt][1] - mx0));
            float p2 = to_tf32(__expf(s[nt][2] - mx1));
            float p3 = to_tf32(__expf(s[nt][3] - mx1));
            sum0 += p0 + p1;
            sum1 += p2 + p3;
            *(float2*)&Ps[m0 + qr][c0]     = make_float2(p0, p1);
            *(float2*)&Ps[m0 + qr + 8][c0] = make_float2(p2, p3);
        }
#pragma unroll
        for (int off = 1; off <= 2; off <<= 1) {
            sum0 += __shfl_xor_sync(0xffffffffu, sum0, off);
            sum1 += __shfl_xor_sync(0xffffffffu, sum1, off);
        }
        lrow[0] = lrow[0] * alpha0 + sum0;
        lrow[1] = lrow[1] * alpha1 + sum1;
#pragma unroll
        for (int nt = 0; nt < 8; nt++) {
            o[nt][0] *= alpha0; o[nt][1] *= alpha0;
            o[nt][2] *= alpha1; o[nt][3] *= alpha1;
        }
        __syncwarp();

#pragma unroll
        for (int kk8 = 0; kk8 < 16; kk8++) {
            const int kc = kk8 * 8;
            uint32_t a[4];
            a[0] = __float_as_uint(Ps[m0 + qr][kc + qk]);
            a[1] = __float_as_uint(Ps[m0 + qr + 8][kc + qk]);
            a[2] = __float_as_uint(Ps[m0 + qr][kc + qk + 4]);
            a[3] = __float_as_uint(Ps[m0 + qr + 8][kc + qk + 4]);
#pragma unroll
            for (int np = 0; np < 4; np++) {
                float4 bb = VF4[(kk8 * 4 + np) * 32 + lane];
                uint32_t b01[2] = {__float_as_uint(bb.x), __float_as_uint(bb.y)};
                uint32_t b23[2] = {__float_as_uint(bb.z), __float_as_uint(bb.w)};
                mma_tf32(o[2 * np], a, b01);
                mma_tf32(o[2 * np + 1], a, b23);
            }
        }
        __syncthreads();
    }

    // epilogue: stage O (rounded) into two A-frag tiles, stream to g_attnf
    const float inv0 = 1.f / lrow[0], inv1 = 1.f / lrow[1];
    const int rl0 = m0 + qr;
#pragma unroll
    for (int nt = 0; nt < 8; nt++) {
        int cc = nt * 8 + 2 * qk;
        float v00 = to_tf32(o[nt][0] * inv0);
        float v01 = to_tf32(o[nt][1] * inv0);
        float v10 = to_tf32(o[nt][2] * inv1);
        float v11 = to_tf32(o[nt][3] * inv1);
        int tb0 = (cc >> 5) * 4096;
        int tb1 = ((cc + 1) >> 5) * 4096;
        smf[tb0 + af_index(rl0, cc & 31)]         = v00;
        smf[tb1 + af_index(rl0, (cc + 1) & 31)]   = v01;
        smf[tb0 + af_index(rl0 + 8, cc & 31)]     = v10;
        smf[tb1 + af_index(rl0 + 8, (cc + 1) & 31)] = v11;
    }
    __syncthreads();
    {
        float* dst = g_attnf +
            (((size_t)(b * 8 + i0 / 128)) * 24 + h * 2) * 4096;
#pragma unroll
        for (int j = 0; j < 8; j++) {
            int i = (j * 256 + tid) * 4;
            *(float4*)(dst + i) = *(const float4*)(smf + i);
        }
    }
}

}  // namespace

extern "C" void kernel_launch(void* const* d_in, const int* in_sizes, int n_in,
                              void* d_out, int out_size) {
    (void)in_sizes; (void)n_in; (void)out_size;
    const float* x  = (const float*)d_in[0];   // (B,1,S,E)
    const float* kp = (const float*)d_in[1];   // (H,E,P)
    const float* vp = (const float*)d_in[2];   // (H,E,P)
    const float* qh = (const float*)d_in[3];   // (H,S,S)
    const float* lw = (const float*)d_in[4];   // (1,HP,E)
    float* out = (float*)d_out;                // (B,S,E)

    cudaFuncSetAttribute(mma_gemm<128, 0>,
                         cudaFuncAttributeMaxDynamicSharedMemorySize, SMG128);
    cudaFuncSetAttribute(mma_gemm<64, 1>,
                         cudaFuncAttributeMaxDynamicSharedMemorySize, SMG64);
    cudaFuncSetAttribute(mma_gemm<128, 2>,
                         cudaFuncAttributeMaxDynamicSharedMemorySize, SMG128);
    cudaFuncSetAttribute(flash_mma,
                         cudaFuncAttributeMaxDynamicSharedMemorySize, SMEM_FLASH);

    round_weights<<<dim3(24, 18), 256>>>(kp, vp, lw);
    mma_gemm<128, 0><<<dim3(Sc / 128, Hc, Bc), 256, SMG128>>>(x, nullptr);
    mma_gemm<64, 1><<<dim3(Sc / 128, Hc, Bc), 256, SMG64>>>(qh, nullptr);
    flash_mma<<<dim3(Sc / 128, Hc, Bc), 256, SMEM_FLASH>>>();
    mma_gemm<128, 2><<<dim3(Bc * Sc / 128, Ec / 128), 256, SMG128>>>(nullptr, out);
}

// round 15
// speedup vs baseline: 1.7826x; 1.6652x over previous
#include <cuda_runtime.h>
#include <cuda_fp16.h>
#include <math.h>
#include <stdint.h>

namespace {

constexpr int Bc = 8, Sc = 1024, Ec = 768, Hc = 12, Pc = 64, HPc = 768;

// fp16 scratch (uint32 = half2). Layout docs at each index fn.
__device__ float    g_k[Bc * Hc * Sc * Pc];          // fp32 raw (flash Q src)
__device__ uint32_t g_qvf_u[96 * 8 * 4096];          // flash K tiles (B-frag)
__device__ uint32_t g_vf_u[96 * 8 * 4096];           // flash V tiles (B-frag)
__device__ uint32_t g_vbf_u[96 * 32 * 1024];         // qv B chunks (B-frag, NT64)
__device__ uint32_t g_attnf_u[64 * 24 * 2048];       // lift A chunks (A-frag)
__device__ uint32_t g_wkvf_u[12 * 24 * 2048];        // proj B chunks (B-frag, NT128)
__device__ uint32_t g_lwf_u[6 * 24 * 2048];          // lift B chunks
__device__ uint32_t g_xf_u[64 * 24 * 2048];          // proj A chunks (A-frag)
__device__ uint32_t g_qhf_u[96 * 32 * 2048];         // qv A chunks (A-frag)

__device__ __forceinline__ uint32_t h2u(float lo, float hi) {
    __half2 h = __floats2half2_rn(lo, hi);
    return *(uint32_t*)&h;
}

__device__ __forceinline__ void mma_f16(float c[4], const uint32_t a[4],
                                        uint32_t b0, uint32_t b1) {
    asm volatile(
        "mma.sync.aligned.m16n8k16.row.col.f32.f16.f16.f32 "
        "{%0,%1,%2,%3}, {%4,%5,%6,%7}, {%8,%9}, {%0,%1,%2,%3};"
        : "+f"(c[0]), "+f"(c[1]), "+f"(c[2]), "+f"(c[3])
        : "r"(a[0]), "r"(a[1]), "r"(a[2]), "r"(a[3]), "r"(b0), "r"(b1));
}

__device__ __forceinline__ uint32_t smem_u32(const void* p) {
    uint32_t a;
    asm("{ .reg .u64 t; cvta.to.shared.u64 t, %1; cvt.u32.u64 %0, t; }"
        : "=r"(a) : "l"(p));
    return a;
}
__device__ __forceinline__ void cp_async16(uint32_t dst, const void* src) {
    asm volatile("cp.async.cg.shared.global [%0], [%1], 16;"
                 :: "r"(dst), "l"(src) : "memory");
}
#define CP_COMMIT() asm volatile("cp.async.commit_group;" ::: "memory")
#define CP_WAIT0()  asm volatile("cp.async.wait_group 0;" ::: "memory")

// ---- half-index maps (value position -> half index within one chunk) ----
// B-frag chunk (32 k x NT n): half idx of B[k][n]
template <int NT>
__device__ __forceinline__ int bmap(int k, int n) {
    int kg = k >> 4, kl = k & 15, f = n >> 3, qr = n & 7;
    int u = (kg * (NT / 16) + (f >> 1)) * 128 +
            (qr * 4 + ((kl & 7) >> 1)) * 4 + (f & 1) * 2 + ((kl >> 3) & 1);
    return u * 2 + (kl & 1);
}
// A-frag chunk (128 m x 32 k): half idx of A[m][k]
__device__ __forceinline__ int amap(int m, int k) {
    int kg = k >> 4, kl = k & 15;
    int u = ((m >> 4) * 2 + kg) * 128 +
            ((m & 7) * 4 + ((kl & 7) >> 1)) * 4 + ((m >> 3) & 1) +
            ((kl >> 3) & 1) * 2;
    return u * 2 + (kl & 1);
}
// flash K tile (128 j x 64 p): n=j, k=p  (B-frag, NT=128, K=64 -> 4 kgroups)
__device__ __forceinline__ int kmap(int j, int p) {
    int kg = p >> 4, kl = p & 15, f = j >> 3, qr = j & 7;
    int u = (kg * 8 + (f >> 1)) * 128 +
            (qr * 4 + ((kl & 7) >> 1)) * 4 + (f & 1) * 2 + ((kl >> 3) & 1);
    return u * 2 + (kl & 1);
}
// flash V tile (128 j x 64 p): n=p, k=j  (B-frag, NT=64, K=128 -> 8 kgroups)
__device__ __forceinline__ int vmap(int j, int p) {
    int kg = j >> 4, kl = j & 15, f = p >> 3, qr = p & 7;
    int u = (kg * 4 + (f >> 1)) * 128 +
            (qr * 4 + ((kl & 7) >> 1)) * 4 + (f & 1) * 2 + ((kl >> 3) & 1);
    return u * 2 + (kl & 1);
}

// ---------------------------------------------------------------------------
// Prologue A: weights -> fp16 B-frag chunks. grid (24, 18).
// ---------------------------------------------------------------------------
__global__ __launch_bounds__(256)
void round_wb(const float* __restrict__ kp, const float* __restrict__ vp,
              const float* __restrict__ lw) {
    __shared__ uint32_t sms[2048];
    __half* hs = (__half*)sms;
    const int t = blockIdx.x, y = blockIdx.y, tid = threadIdx.x;
#pragma unroll
    for (int j = 0; j < 16; j++) {
        int i = j * 256 + tid;
        int kk = i >> 7, n = i & 127;
        float val;
        if (y < Hc) {
            int e = t * 32 + kk;
            val = (n < 64) ? kp[((size_t)y * Ec + e) * Pc + n]
                           : vp[((size_t)y * Ec + e) * Pc + (n - 64)];
        } else {
            val = lw[(size_t)(t * 32 + kk) * Ec + (y - Hc) * 128 + n];
        }
        hs[bmap<128>(kk, n)] = __float2half_rn(val);
    }
    __syncthreads();
    uint32_t* dst = (y < Hc) ? g_wkvf_u + ((size_t)y * 24 + t) * 2048
                             : g_lwf_u + ((size_t)(y - Hc) * 24 + t) * 2048;
#pragma unroll
    for (int j = 0; j < 2; j++) {
        int u = (j * 256 + tid) * 4;
        *(uint4*)(dst + u) = *(const uint4*)(sms + u);
    }
}

// Prologue B: x -> A-frag chunks. grid (24, 64): rb = b*8 + rowblock.
__global__ __launch_bounds__(256)
void round_xa(const float* __restrict__ x) {
    __shared__ uint32_t sms[2048];
    __half* hs = (__half*)sms;
    const int t = blockIdx.x, rb = blockIdx.y, tid = threadIdx.x;
#pragma unroll
    for (int j = 0; j < 16; j++) {
        int i = j * 256 + tid;
        int m = i >> 5, kl = i & 31;
        float val = x[(size_t)(rb * 128 + m) * Ec + t * 32 + kl];
        hs[amap(m, kl)] = __float2half_rn(val);
    }
    __syncthreads();
    uint32_t* dst = g_xf_u + ((size_t)rb * 24 + t) * 2048;
#pragma unroll
    for (int j = 0; j < 2; j++) {
        int u = (j * 256 + tid) * 4;
        *(uint4*)(dst + u) = *(const uint4*)(sms + u);
    }
}

// Prologue C: q_heads -> A-frag chunks. grid (32, 8, 12).
__global__ __launch_bounds__(256)
void round_qha(const float* __restrict__ qh) {
    __shared__ uint32_t sms[2048];
    __half* hs = (__half*)sms;
    const int t = blockIdx.x, rb = blockIdx.y, h = blockIdx.z;
    const int tid = threadIdx.x;
#pragma unroll
    for (int j = 0; j < 16; j++) {
        int i = j * 256 + tid;
        int m = i >> 5, kl = i & 31;
        float val = qh[((size_t)h * Sc + rb * 128 + m) * Sc + t * 32 + kl];
        hs[amap(m, kl)] = __float2half_rn(val);
    }
    __syncthreads();
    uint32_t* dst = g_qhf_u + (((size_t)h * 8 + rb) * 32 + t) * 2048;
#pragma unroll
    for (int j = 0; j < 2; j++) {
        int u = (j * 256 + tid) * 4;
        *(uint4*)(dst + u) = *(const uint4*)(sms + u);
    }
}

// ---------------------------------------------------------------------------
// fp16 mma.sync GEMM, fully cp.async, double-buffered, k-step 32.
// MODE 0: proj (NT=128)  MODE 1: qv (NT=64)  MODE 2: lift (NT=128)
// ---------------------------------------------------------------------------
template <int NT, int MODE>
__global__ __launch_bounds__(256, 2)
void mma_gemm(float* __restrict__ Out) {
    constexpr int MT = (NT == 128) ? 4 : 2;     // warp m-tiles (WM 64/32)
    constexpr int BCH = NT * 16;                // B chunk u32
    constexpr int NTK = (MODE == 1) ? 32 : 24;  // k-chunks

    extern __shared__ uint32_t smu[];
    const uint4* AU4 = (const uint4*)smu;
    const uint4* BU4 = (const uint4*)(smu + 2 * 2048);
    const uint32_t as_base = smem_u32(smu);
    const uint32_t bs_base = smem_u32(smu + 2 * 2048);

    const int tid = threadIdx.x;
    const int wid = tid >> 5, lane = tid & 31;
    const int wr = (NT == 128) ? (wid >> 2) : (wid >> 1);
    const int wc = (NT == 128) ? (wid & 3) : (wid & 1);
    const int wm0 = wr * ((NT == 128) ? 64 : 32), wn0 = wc * 32;
    const int qk = lane & 3, qr = lane >> 2;
    const int mtile0 = wm0 >> 4;

    const int bx = blockIdx.x, hy = blockIdx.y, bz = blockIdx.z;
    const int row0 = bx * 128;
    const int bh = bz * Hc + hy;

    const uint32_t* Agf;
    const uint32_t* Bgf;
    int n0g = 0;
    if (MODE == 0) {
        Agf = g_xf_u + ((size_t)(bz * 8 + bx)) * 24 * 2048;
        Bgf = g_wkvf_u + (size_t)hy * 24 * 2048;
    } else if (MODE == 1) {
        Agf = g_qhf_u + ((size_t)(hy * 8 + bx)) * 32 * 2048;
        Bgf = g_vbf_u + (size_t)bh * 32 * 1024;
    } else {
        Agf = g_attnf_u + (size_t)bx * 24 * 2048;
        Bgf = g_lwf_u + (size_t)blockIdx.y * 24 * 2048;
        n0g = blockIdx.y * 128;
    }

    float c[MT][4][4];
#pragma unroll
    for (int mt = 0; mt < MT; mt++)
#pragma unroll
        for (int nt = 0; nt < 4; nt++)
#pragma unroll
            for (int q = 0; q < 4; q++) c[mt][nt][q] = 0.f;

    auto fill = [&](int t) {
        const int buf = t & 1;
        const uint32_t* asrc = Agf + (size_t)t * 2048;
#pragma unroll
        for (int j = 0; j < 2; j++) {
            int u = (j * 256 + tid) * 4;
            cp_async16(as_base + (buf * 2048 + u) * 4, asrc + u);
        }
        const uint32_t* bsrc = Bgf + (size_t)t * BCH;
#pragma unroll
        for (int j = 0; j < BCH / 1024; j++) {
            int u = (j * 256 + tid) * 4;
            cp_async16(bs_base + (buf * BCH + u) * 4, bsrc + u);
        }
        CP_COMMIT();
    };

    fill(0);
    CP_WAIT0();
    __syncthreads();

    for (int t = 0; t < NTK; t++) {
        if (t + 1 < NTK) fill(t + 1);
        const int a4 = (t & 1) * 512, b4 = (t & 1) * (BCH / 4);
#pragma unroll
        for (int kg = 0; kg < 2; kg++) {
            uint32_t a[MT][4];
#pragma unroll
            for (int mt = 0; mt < MT; mt++) {
                uint4 av = AU4[a4 + ((mtile0 + mt) * 2 + kg) * 32 + lane];
                a[mt][0] = av.x; a[mt][1] = av.y; a[mt][2] = av.z; a[mt][3] = av.w;
            }
#pragma unroll
            for (int j = 0; j < 2; j++) {
                uint4 bb = BU4[b4 + (kg * (NT / 16) + wc * 2 + j) * 32 + lane];
#pragma unroll
                for (int mt = 0; mt < MT; mt++) {
                    mma_f16(c[mt][2 * j], a[mt], bb.x, bb.y);
                    mma_f16(c[mt][2 * j + 1], a[mt], bb.z, bb.w);
                }
            }
        }
        if (t + 1 < NTK) CP_WAIT0();
        __syncthreads();
    }

    // ---- epilogue ----
    __half* hst = (__half*)smu;
#pragma unroll
    for (int mt = 0; mt < MT; mt++) {
#pragma unroll
        for (int nt = 0; nt < 4; nt++) {
            int rl = wm0 + mt * 16 + qr;
            int col = wn0 + nt * 8 + 2 * qk;
            float v00 = c[mt][nt][0], v01 = c[mt][nt][1];
            float v10 = c[mt][nt][2], v11 = c[mt][nt][3];
            if (MODE == 0) {
                if (col < 64) {     // k: fp32 raw
                    size_t off = (size_t)bh * Sc * Pc;
                    *(float2*)(g_k + off + (size_t)(row0 + rl) * Pc + col) =
                        make_float2(v00, v01);
                    *(float2*)(g_k + off + (size_t)(row0 + rl + 8) * Pc + col) =
                        make_float2(v10, v11);
                } else {            // v: flash-V frag + qv-B frag (fp16)
                    int cc = col - 64;
                    __half h00 = __float2half_rn(v00), h01 = __float2half_rn(v01);
                    __half h10 = __float2half_rn(v10), h11 = __float2half_rn(v11);
                    hst[vmap(rl, cc)]         = h00;
                    hst[vmap(rl, cc + 1)]     = h01;
                    hst[vmap(rl + 8, cc)]     = h10;
                    hst[vmap(rl + 8, cc + 1)] = h11;
                    int base0 = (4096 + (rl >> 5) * 1024) * 2;
                    int base1 = (4096 + ((rl + 8) >> 5) * 1024) * 2;
                    hst[base0 + bmap<64>(rl & 31, cc)]           = h00;
                    hst[base0 + bmap<64>(rl & 31, cc + 1)]       = h01;
                    hst[base1 + bmap<64>((rl + 8) & 31, cc)]     = h10;
                    hst[base1 + bmap<64>((rl + 8) & 31, cc + 1)] = h11;
                }
            } else if (MODE == 1) {  // qv -> flash-K frag (fp16)
                hst[kmap(rl, col)]         = __float2half_rn(v00);
                hst[kmap(rl, col + 1)]     = __float2half_rn(v01);
                hst[kmap(rl + 8, col)]     = __float2half_rn(v10);
                hst[kmap(rl + 8, col + 1)] = __float2half_rn(v11);
            } else {                 // lift -> fp32 out
                int row = row0 + rl;
                *(float2*)(Out + (size_t)row * Ec + n0g + col) =
                    make_float2(v00, v01);
                *(float2*)(Out + (size_t)(row + 8) * Ec + n0g + col) =
                    make_float2(v10, v11);
            }
        }
    }
    if (MODE == 0) {
        __syncthreads();
        uint32_t* d1 = g_vf_u + ((size_t)bh * 8 + bx) * 4096;
        uint32_t* d2 = g_vbf_u + (size_t)bh * 32 * 1024 + (size_t)bx * 4096;
#pragma unroll
        for (int j = 0; j < 4; j++) {
            int u = (j * 256 + tid) * 4;
            *(uint4*)(d1 + u) = *(const uint4*)(smu + u);
            *(uint4*)(d2 + u) = *(const uint4*)(smu + 4096 + u);
        }
    } else if (MODE == 1) {
        __syncthreads();
        uint32_t* d1 = g_qvf_u + ((size_t)bh * 8 + bx) * 4096;
#pragma unroll
        for (int j = 0; j < 4; j++) {
            int u = (j * 256 + tid) * 4;
            *(uint4*)(d1 + u) = *(const uint4*)(smu + u);
        }
    }
}

constexpr int SMG128 = (2 * 2048 + 2 * 2048) * 4;   // 32 KB
constexpr int SMG64  = (2 * 2048 + 2 * 1024) * 4;   // 24 KB

// ---------------------------------------------------------------------------
// Flash attention, fp16 mma, P entirely in registers (fp16 C->A frag match).
// Smem: KF[2][4096 u32], VF[2][4096 u32] = 64 KB.
// ---------------------------------------------------------------------------
constexpr int SMEM_FLASH = 4 * 4096 * 4;

__global__ __launch_bounds__(256, 1)
void flash_mma() {
    extern __shared__ uint32_t smu[];
    const uint4* KU4 = (const uint4*)smu;
    const uint4* VU4 = (const uint4*)(smu + 2 * 4096);
    const uint32_t ks_base = smem_u32(smu);
    const uint32_t vs_base = smem_u32(smu + 2 * 4096);

    const int i0 = (gridDim.x - 1 - blockIdx.x) * 128;  // heavy blocks first
    const int h = blockIdx.y, b = blockIdx.z;
    const int tid = threadIdx.x;
    const int wid = tid >> 5, lane = tid & 31;
    const int qk = lane & 3, qr = lane >> 2;
    const int m0 = wid * 16;

    const int bh = b * Hc + h;
    const float2* kb2 = (const float2*)(g_k + (size_t)bh * Sc * Pc);
    const uint32_t* kfb = g_qvf_u + (size_t)bh * 8 * 4096;
    const uint32_t* vfb = g_vf_u + (size_t)bh * 8 * 4096;
    const float qscale = rsqrtf((float)Ec);

    // Q A-frags (fp16) from raw g_k
    uint32_t qa[4][4];
    {
        const int r0g = i0 + m0 + qr, r1g = r0g + 8;
#pragma unroll
        for (int kg = 0; kg < 4; kg++) {
            int c0 = kg * 16 + 2 * qk;
            float2 x0 = kb2[(size_t)r0g * 32 + (c0 >> 1)];
            float2 x1 = kb2[(size_t)r1g * 32 + (c0 >> 1)];
            float2 x2 = kb2[(size_t)r0g * 32 + ((c0 + 8) >> 1)];
            float2 x3 = kb2[(size_t)r1g * 32 + ((c0 + 8) >> 1)];
            qa[kg][0] = h2u(x0.x * qscale, x0.y * qscale);
            qa[kg][1] = h2u(x1.x * qscale, x1.y * qscale);
            qa[kg][2] = h2u(x2.x * qscale, x2.y * qscale);
            qa[kg][3] = h2u(x3.x * qscale, x3.y * qscale);
        }
    }

    auto fill = [&](int t) {
        const int buf = t & 1;
        const uint32_t* ksrc = kfb + (size_t)t * 4096;
        const uint32_t* vsrc = vfb + (size_t)t * 4096;
#pragma unroll
        for (int j = 0; j < 4; j++) {
            int u = (j * 256 + tid) * 4;
            cp_async16(ks_base + (buf * 4096 + u) * 4, ksrc + u);
            cp_async16(vs_base + (buf * 4096 + u) * 4, vsrc + u);
        }
        CP_COMMIT();
    };

    float mrow[2] = {-INFINITY, -INFINITY};
    float lrow[2] = {0.f, 0.f};
    float o[8][4];
#pragma unroll
    for (int nt = 0; nt < 8; nt++)
#pragma unroll
        for (int q = 0; q < 4; q++) o[nt][q] = 0.f;

    const int tN = i0 / 128 + 1;
    fill(0);

    for (int t = 0; t < tN; t++) {
        if (t + 1 < tN) fill(t + 1);
        if (t + 1 < tN)
            asm volatile("cp.async.wait_group 1;" ::: "memory");
        else
            asm volatile("cp.async.wait_group 0;" ::: "memory");
        __syncthreads();
        const int kb4 = (t & 1) * 1024;

        // S = Q @ K^T : 16 n-frags, 4 kgroups -> 64 HMMA
        float s[16][4];
#pragma unroll
        for (int nt = 0; nt < 16; nt++)
#pragma unroll
            for (int q = 0; q < 4; q++) s[nt][q] = 0.f;

#pragma unroll
        for (int kg = 0; kg < 4; kg++) {
#pragma unroll
            for (int fp = 0; fp < 8; fp++) {
                uint4 bb = KU4[kb4 + (kg * 8 + fp) * 32 + lane];
                mma_f16(s[2 * fp], qa[kg], bb.x, bb.y);
                mma_f16(s[2 * fp + 1], qa[kg], bb.z, bb.w);
            }
        }

        if (t == tN - 1) {  // diagonal block: causal mask (local indices)
            int r0 = m0 + qr, r1 = r0 + 8;
#pragma unroll
            for (int nt = 0; nt < 16; nt++) {
                int c0 = nt * 8 + 2 * qk;
                if (c0 > r0)     s[nt][0] = -INFINITY;
                if (c0 + 1 > r0) s[nt][1] = -INFINITY;
                if (c0 > r1)     s[nt][2] = -INFINITY;
                if (c0 + 1 > r1) s[nt][3] = -INFINITY;
            }
        }

        // online softmax; p packed to fp16 A-frags in registers
        float mx0 = mrow[0], mx1 = mrow[1];
#pragma unroll
        for (int nt = 0; nt < 16; nt++) {
            mx0 = fmaxf(mx0, fmaxf(s[nt][0], s[nt][1]));
            mx1 = fmaxf(mx1, fmaxf(s[nt][2], s[nt][3]));
        }
#pragma unroll
        for (int off = 1; off <= 2; off <<= 1) {
            mx0 = fmaxf(mx0, __shfl_xor_sync(0xffffffffu, mx0, off));
            mx1 = fmaxf(mx1, __shfl_xor_sync(0xffffffffu, mx1, off));
        }
        float alpha0 = __expf(mrow[0] - mx0);
        float alpha1 = __expf(mrow[1] - mx1);
        mrow[0] = mx0; mrow[1] = mx1;
        float sum0 = 0.f, sum1 = 0.f;
        uint32_t plo[16], phi[16];
#pragma unroll
        for (int nt = 0; nt < 16; nt++) {
            float p0 = __expf(s[nt][0] - mx0);
            float p1 = __expf(s[nt][1] - mx0);
            float p2 = __expf(s[nt][2] - mx1);
            float p3 = __expf(s[nt][3] - mx1);
            uint32_t lo = h2u(p0, p1), hi = h2u(p2, p3);
            plo[nt] = lo; phi[nt] = hi;
            float2 lf = __half22float2(*(__half2*)&lo);
            float2 hf = __half22float2(*(__half2*)&hi);
            sum0 += lf.x + lf.y;
            sum1 += hf.x + hf.y;
        }
#pragma unroll
        for (int off = 1; off <= 2; off <<= 1) {
            sum0 += __shfl_xor_sync(0xffffffffu, sum0, off);
            sum1 += __shfl_xor_sync(0xffffffffu, sum1, off);
        }
        lrow[0] = lrow[0] * alpha0 + sum0;
        lrow[1] = lrow[1] * alpha1 + sum1;
#pragma unroll
        for (int nt = 0; nt < 8; nt++) {
            o[nt][0] *= alpha0; o[nt][1] *= alpha0;
            o[nt][2] *= alpha1; o[nt][3] *= alpha1;
        }

        // O += P @ V : 8 kgroups x 8 n-frags -> 64 HMMA, A straight from regs
#pragma unroll
        for (int kg = 0; kg < 8; kg++) {
            uint32_t a[4] = {plo[2 * kg], phi[2 * kg],
                             plo[2 * kg + 1], phi[2 * kg + 1]};
#pragma unroll
            for (int fp = 0; fp < 4; fp++) {
                uint4 vv = VU4[kb4 + (kg * 4 + fp) * 32 + lane];
                mma_f16(o[2 * fp], a, vv.x, vv.y);
                mma_f16(o[2 * fp + 1], a, vv.z, vv.w);
            }
        }
        __syncthreads();  // all warps done with buf before refill
    }

    // epilogue: O -> fp16 A-frag chunks for lift (staged, coalesced out)
    const float inv0 = 1.f / lrow[0], inv1 = 1.f / lrow[1];
    const int rl0 = m0 + qr;
    __half* hst = (__half*)smu;
#pragma unroll
    for (int nt = 0; nt < 8; nt++) {
        int cc = nt * 8 + 2 * qk;
        int ch0 = (cc >> 5) * 4096, ch1 = ((cc + 1) >> 5) * 4096;
        hst[ch0 + amap(rl0, cc & 31)]           = __float2half_rn(o[nt][0] * inv0);
        hst[ch1 + amap(rl0, (cc + 1) & 31)]     = __float2half_rn(o[nt][1] * inv0);
        hst[ch0 + amap(rl0 + 8, cc & 31)]       = __float2half_rn(o[nt][2] * inv1);
        hst[ch1 + amap(rl0 + 8, (cc + 1) & 31)] = __float2half_rn(o[nt][3] * inv1);
    }
    __syncthreads();
    {
        uint32_t* dst = g_attnf_u +
            (((size_t)(b * 8 + i0 / 128)) * 24 + h * 2) * 2048;
#pragma unroll
        for (int j = 0; j < 4; j++) {
            int u = (j * 256 + tid) * 4;
            *(uint4*)(dst + u) = *(const uint4*)(smu + u);
        }
    }
}

}  // namespace

extern "C" void kernel_launch(void* const* d_in, const int* in_sizes, int n_in,
                              void* d_out, int out_size) {
    (void)in_sizes; (void)n_in; (void)out_size;
    const float* x  = (const float*)d_in[0];   // (B,1,S,E)
    const float* kp = (const float*)d_in[1];   // (H,E,P)
    const float* vp = (const float*)d_in[2];   // (H,E,P)
    const float* qh = (const float*)d_in[3];   // (H,S,S)
    const float* lw = (const float*)d_in[4];   // (1,HP,E)
    float* out = (float*)d_out;                // (B,S,E)

    cudaFuncSetAttribute(mma_gemm<128, 0>,
                         cudaFuncAttributeMaxDynamicSharedMemorySize, SMG128);
    cudaFuncSetAttribute(mma_gemm<64, 1>,
                         cudaFuncAttributeMaxDynamicSharedMemorySize, SMG64);
    cudaFuncSetAttribute(mma_gemm<128, 2>,
                         cudaFuncAttributeMaxDynamicSharedMemorySize, SMG128);
    cudaFuncSetAttribute(flash_mma,
                         cudaFuncAttributeMaxDynamicSharedMemorySize, SMEM_FLASH);

    round_wb<<<dim3(24, 18), 256>>>(kp, vp, lw);
    round_xa<<<dim3(24, 64), 256>>>(x);
    round_qha<<<dim3(32, 8, 12), 256>>>(qh);
    mma_gemm<128, 0><<<dim3(Sc / 128, Hc, Bc), 256, SMG128>>>(nullptr);
    mma_gemm<64, 1><<<dim3(Sc / 128, Hc, Bc), 256, SMG64>>>(nullptr);
    flash_mma<<<dim3(Sc / 128, Hc, Bc), 256, SMEM_FLASH>>>();
    mma_gemm<128, 2><<<dim3(Bc * Sc / 128, Ec / 128), 256, SMG128>>>(out);
}

// round 16
// speedup vs baseline: 1.9366x; 1.0864x over previous
#include <cuda_runtime.h>
#include <cuda_fp16.h>
#include <math.h>
#include <stdint.h>

namespace {

constexpr int Bc = 8, Sc = 1024, Ec = 768, Hc = 12, Pc = 64, HPc = 768;

// fp16 scratch (uint32 = half2). Layout docs at each index fn.
__device__ float    g_k[Bc * Hc * Sc * Pc];          // fp32 raw (flash Q src)
__device__ uint32_t g_qvf_u[96 * 8 * 4096];          // flash K tiles (B-frag)
__device__ uint32_t g_vf_u[96 * 8 * 4096];           // flash V tiles (B-frag)
__device__ uint32_t g_vbf_u[96 * 32 * 1024];         // qv B chunks (B-frag, NT64)
__device__ uint32_t g_attnf_u[64 * 24 * 2048];       // lift A chunks (A-frag)
__device__ uint32_t g_wkvf_u[12 * 24 * 2048];        // proj B chunks (B-frag, NT128)
__device__ uint32_t g_lwf_u[6 * 24 * 2048];          // lift B chunks
__device__ uint32_t g_xf_u[64 * 24 * 2048];          // proj A chunks (A-frag)
__device__ uint32_t g_qhf_u[96 * 32 * 2048];         // qv A chunks (A-frag)

__device__ __forceinline__ uint32_t h2u(float lo, float hi) {
    __half2 h = __floats2half2_rn(lo, hi);
    return *(uint32_t*)&h;
}

__device__ __forceinline__ void mma_f16(float c[4], const uint32_t a[4],
                                        uint32_t b0, uint32_t b1) {
    asm volatile(
        "mma.sync.aligned.m16n8k16.row.col.f32.f16.f16.f32 "
        "{%0,%1,%2,%3}, {%4,%5,%6,%7}, {%8,%9}, {%0,%1,%2,%3};"
        : "+f"(c[0]), "+f"(c[1]), "+f"(c[2]), "+f"(c[3])
        : "r"(a[0]), "r"(a[1]), "r"(a[2]), "r"(a[3]), "r"(b0), "r"(b1));
}

__device__ __forceinline__ uint32_t smem_u32(const void* p) {
    uint32_t a;
    asm("{ .reg .u64 t; cvta.to.shared.u64 t, %1; cvt.u32.u64 %0, t; }"
        : "=r"(a) : "l"(p));
    return a;
}
__device__ __forceinline__ void cp_async16(uint32_t dst, const void* src) {
    asm volatile("cp.async.cg.shared.global [%0], [%1], 16;"
                 :: "r"(dst), "l"(src) : "memory");
}
#define CP_COMMIT() asm volatile("cp.async.commit_group;" ::: "memory")
__device__ __forceinline__ void cp_wait_n(int n) {
    if (n <= 0)      asm volatile("cp.async.wait_group 0;" ::: "memory");
    else if (n == 1) asm volatile("cp.async.wait_group 1;" ::: "memory");
    else if (n == 2) asm volatile("cp.async.wait_group 2;" ::: "memory");
    else             asm volatile("cp.async.wait_group 3;" ::: "memory");
}

// ---- half-index maps (value position -> half index within one chunk) ----
template <int NT>
__device__ __forceinline__ int bmap(int k, int n) {
    int kg = k >> 4, kl = k & 15, f = n >> 3, qr = n & 7;
    int u = (kg * (NT / 16) + (f >> 1)) * 128 +
            (qr * 4 + ((kl & 7) >> 1)) * 4 + (f & 1) * 2 + ((kl >> 3) & 1);
    return u * 2 + (kl & 1);
}
__device__ __forceinline__ int amap(int m, int k) {
    int kg = k >> 4, kl = k & 15;
    int u = ((m >> 4) * 2 + kg) * 128 +
            ((m & 7) * 4 + ((kl & 7) >> 1)) * 4 + ((m >> 3) & 1) +
            ((kl >> 3) & 1) * 2;
    return u * 2 + (kl & 1);
}
__device__ __forceinline__ int kmap(int j, int p) {
    int kg = p >> 4, kl = p & 15, f = j >> 3, qr = j & 7;
    int u = (kg * 8 + (f >> 1)) * 128 +
            (qr * 4 + ((kl & 7) >> 1)) * 4 + (f & 1) * 2 + ((kl >> 3) & 1);
    return u * 2 + (kl & 1);
}
__device__ __forceinline__ int vmap(int j, int p) {
    int kg = j >> 4, kl = j & 15, f = p >> 3, qr = p & 7;
    int u = (kg * 4 + (f >> 1)) * 128 +
            (qr * 4 + ((kl & 7) >> 1)) * 4 + (f & 1) * 2 + ((kl >> 3) & 1);
    return u * 2 + (kl & 1);
}

// ---------------------------------------------------------------------------
// Fused prologue: all fp16 frag-order conversions in ONE launch.
// blocks [0,432): weights;  [432,1968): x;  [1968,5040): q_heads.
// ---------------------------------------------------------------------------
__global__ __launch_bounds__(256)
void round_all(const float* __restrict__ kp, const float* __restrict__ vp,
               const float* __restrict__ lw, const float* __restrict__ x,
               const float* __restrict__ qh) {
    __shared__ uint32_t sms[2048];
    __half* hs = (__half*)sms;
    const int bid = blockIdx.x, tid = threadIdx.x;
    uint32_t* dst;
    if (bid < 432) {                       // weights -> B-frag chunks
        const int t = bid % 24, y = bid / 24;
#pragma unroll
        for (int j = 0; j < 16; j++) {
            int i = j * 256 + tid;
            int kk = i >> 7, n = i & 127;
            float val;
            if (y < Hc) {
                int e = t * 32 + kk;
                val = (n < 64) ? kp[((size_t)y * Ec + e) * Pc + n]
                               : vp[((size_t)y * Ec + e) * Pc + (n - 64)];
            } else {
                val = lw[(size_t)(t * 32 + kk) * Ec + (y - Hc) * 128 + n];
            }
            hs[bmap<128>(kk, n)] = __float2half_rn(val);
        }
        dst = (y < Hc) ? g_wkvf_u + ((size_t)y * 24 + t) * 2048
                       : g_lwf_u + ((size_t)(y - Hc) * 24 + t) * 2048;
    } else if (bid < 1968) {               // x -> A-frag chunks
        const int r = bid - 432;
        const int t = r % 24, rb = r / 24;
#pragma unroll
        for (int j = 0; j < 16; j++) {
            int i = j * 256 + tid;
            int m = i >> 5, kl = i & 31;
            float val = x[(size_t)(rb * 128 + m) * Ec + t * 32 + kl];
            hs[amap(m, kl)] = __float2half_rn(val);
        }
        dst = g_xf_u + ((size_t)rb * 24 + t) * 2048;
    } else {                               // q_heads -> A-frag chunks
        const int r = bid - 1968;
        const int t = r % 32, rb = (r / 32) % 8, h = r / 256;
#pragma unroll
        for (int j = 0; j < 16; j++) {
            int i = j * 256 + tid;
            int m = i >> 5, kl = i & 31;
            float val = qh[((size_t)h * Sc + rb * 128 + m) * Sc + t * 32 + kl];
            hs[amap(m, kl)] = __float2half_rn(val);
        }
        dst = g_qhf_u + (((size_t)h * 8 + rb) * 32 + t) * 2048;
    }
    __syncthreads();
#pragma unroll
    for (int j = 0; j < 2; j++) {
        int u = (j * 256 + tid) * 4;
        *(uint4*)(dst + u) = *(const uint4*)(sms + u);
    }
}

// ---------------------------------------------------------------------------
// fp16 mma.sync GEMM, 4-stage cp.async pipeline, k-step 32.
// MODE 0: proj (NT=128)  MODE 1: qv (NT=64)  MODE 2: lift (NT=128)
// ---------------------------------------------------------------------------
constexpr int GSTG = 4;

template <int NT, int MODE>
__global__ __launch_bounds__(256, 2)
void mma_gemm(float* __restrict__ Out) {
    constexpr int MT = (NT == 128) ? 4 : 2;
    constexpr int BCH = NT * 16;                // B chunk u32
    constexpr int NTK = (MODE == 1) ? 32 : 24;

    extern __shared__ uint32_t smu[];
    const uint4* AU4 = (const uint4*)smu;
    const uint4* BU4 = (const uint4*)(smu + GSTG * 2048);
    const uint32_t as_base = smem_u32(smu);
    const uint32_t bs_base = smem_u32(smu + GSTG * 2048);

    const int tid = threadIdx.x;
    const int wid = tid >> 5, lane = tid & 31;
    const int wr = (NT == 128) ? (wid >> 2) : (wid >> 1);
    const int wc = (NT == 128) ? (wid & 3) : (wid & 1);
    const int wm0 = wr * ((NT == 128) ? 64 : 32);
    const int mtile0 = wm0 >> 4;
    const int qk = lane & 3, qr = lane >> 2;
    const int wn0 = wc * 32;

    const int bx = blockIdx.x, hy = blockIdx.y, bz = blockIdx.z;
    const int row0 = bx * 128;
    const int bh = bz * Hc + hy;

    const uint32_t* Agf;
    const uint32_t* Bgf;
    int n0g = 0;
    if (MODE == 0) {
        Agf = g_xf_u + ((size_t)(bz * 8 + bx)) * 24 * 2048;
        Bgf = g_wkvf_u + (size_t)hy * 24 * 2048;
    } else if (MODE == 1) {
        Agf = g_qhf_u + ((size_t)(hy * 8 + bx)) * 32 * 2048;
        Bgf = g_vbf_u + (size_t)bh * 32 * 1024;
    } else {
        Agf = g_attnf_u + (size_t)bx * 24 * 2048;
        Bgf = g_lwf_u + (size_t)blockIdx.y * 24 * 2048;
        n0g = blockIdx.y * 128;
    }

    float c[MT][4][4];
#pragma unroll
    for (int mt = 0; mt < MT; mt++)
#pragma unroll
        for (int nt = 0; nt < 4; nt++)
#pragma unroll
            for (int q = 0; q < 4; q++) c[mt][nt][q] = 0.f;

    auto fill = [&](int t) {
        const int buf = t % GSTG;
        const uint32_t* asrc = Agf + (size_t)t * 2048;
#pragma unroll
        for (int j = 0; j < 2; j++) {
            int u = (j * 256 + tid) * 4;
            cp_async16(as_base + (buf * 2048 + u) * 4, asrc + u);
        }
        const uint32_t* bsrc = Bgf + (size_t)t * BCH;
#pragma unroll
        for (int j = 0; j < BCH / 1024; j++) {
            int u = (j * 256 + tid) * 4;
            cp_async16(bs_base + (buf * BCH + u) * 4, bsrc + u);
        }
        CP_COMMIT();
    };

#pragma unroll
    for (int s = 0; s < GSTG - 1; s++)
        if (s < NTK) fill(s);

    for (int t = 0; t < NTK; t++) {
        int issued = (t + GSTG - 1 < NTK) ? (t + GSTG - 1) : NTK;
        cp_wait_n(issued - (t + 1));
        __syncthreads();
        if (t + GSTG - 1 < NTK) fill(t + GSTG - 1);

        const int a4 = (t % GSTG) * 512, b4 = (t % GSTG) * (BCH / 4);
#pragma unroll
        for (int kg = 0; kg < 2; kg++) {
            uint32_t a[MT][4];
#pragma unroll
            for (int mt = 0; mt < MT; mt++) {
                uint4 av = AU4[a4 + ((mtile0 + mt) * 2 + kg) * 32 + lane];
                a[mt][0] = av.x; a[mt][1] = av.y; a[mt][2] = av.z; a[mt][3] = av.w;
            }
#pragma unroll
            for (int j = 0; j < 2; j++) {
                uint4 bb = BU4[b4 + (kg * (NT / 16) + wc * 2 + j) * 32 + lane];
#pragma unroll
                for (int mt = 0; mt < MT; mt++) {
                    mma_f16(c[mt][2 * j], a[mt], bb.x, bb.y);
                    mma_f16(c[mt][2 * j + 1], a[mt], bb.z, bb.w);
                }
            }
        }
    }
    __syncthreads();

    // ---- epilogue ----
    __half* hst = (__half*)smu;
#pragma unroll
    for (int mt = 0; mt < MT; mt++) {
#pragma unroll
        for (int nt = 0; nt < 4; nt++) {
            int rl = wm0 + mt * 16 + qr;
            int col = wn0 + nt * 8 + 2 * qk;
            float v00 = c[mt][nt][0], v01 = c[mt][nt][1];
            float v10 = c[mt][nt][2], v11 = c[mt][nt][3];
            if (MODE == 0) {
                if (col < 64) {
                    size_t off = (size_t)bh * Sc * Pc;
                    *(float2*)(g_k + off + (size_t)(row0 + rl) * Pc + col) =
                        make_float2(v00, v01);
                    *(float2*)(g_k + off + (size_t)(row0 + rl + 8) * Pc + col) =
                        make_float2(v10, v11);
                } else {
                    int cc = col - 64;
                    __half h00 = __float2half_rn(v00), h01 = __float2half_rn(v01);
                    __half h10 = __float2half_rn(v10), h11 = __float2half_rn(v11);
                    hst[vmap(rl, cc)]         = h00;
                    hst[vmap(rl, cc + 1)]     = h01;
                    hst[vmap(rl + 8, cc)]     = h10;
                    hst[vmap(rl + 8, cc + 1)] = h11;
                    int base0 = (4096 + (rl >> 5) * 1024) * 2;
                    int base1 = (4096 + ((rl + 8) >> 5) * 1024) * 2;
                    hst[base0 + bmap<64>(rl & 31, cc)]           = h00;
                    hst[base0 + bmap<64>(rl & 31, cc + 1)]       = h01;
                    hst[base1 + bmap<64>((rl + 8) & 31, cc)]     = h10;
                    hst[base1 + bmap<64>((rl + 8) & 31, cc + 1)] = h11;
                }
            } else if (MODE == 1) {
                hst[kmap(rl, col)]         = __float2half_rn(v00);
                hst[kmap(rl, col + 1)]     = __float2half_rn(v01);
                hst[kmap(rl + 8, col)]     = __float2half_rn(v10);
                hst[kmap(rl + 8, col + 1)] = __float2half_rn(v11);
            } else {
                int row = row0 + rl;
                *(float2*)(Out + (size_t)row * Ec + n0g + col) =
                    make_float2(v00, v01);
                *(float2*)(Out + (size_t)(row + 8) * Ec + n0g + col) =
                    make_float2(v10, v11);
            }
        }
    }
    if (MODE == 0) {
        __syncthreads();
        uint32_t* d1 = g_vf_u + ((size_t)bh * 8 + bx) * 4096;
        uint32_t* d2 = g_vbf_u + (size_t)bh * 32 * 1024 + (size_t)bx * 4096;
#pragma unroll
        for (int j = 0; j < 4; j++) {
            int u = (j * 256 + tid) * 4;
            *(uint4*)(d1 + u) = *(const uint4*)(smu + u);
            *(uint4*)(d2 + u) = *(const uint4*)(smu + 4096 + u);
        }
    } else if (MODE == 1) {
        __syncthreads();
        uint32_t* d1 = g_qvf_u + ((size_t)bh * 8 + bx) * 4096;
#pragma unroll
        for (int j = 0; j < 4; j++) {
            int u = (j * 256 + tid) * 4;
            *(uint4*)(d1 + u) = *(const uint4*)(smu + u);
        }
    }
}

constexpr int SMG128 = GSTG * (2048 + 2048) * 4;   // 96 KB
constexpr int SMG64  = GSTG * (2048 + 1024) * 4;   // 48 KB

// ---------------------------------------------------------------------------
// Flash attention, fp16 mma, P in registers, 3-stage K/V pipeline,
// ONE barrier per tile.  Smem: K[3][4096 u32] + V[3][4096 u32] = 96 KB.
// ---------------------------------------------------------------------------
constexpr int FSTG = 3;
constexpr int SMEM_FLASH = 2 * FSTG * 4096 * 4;

__global__ __launch_bounds__(256, 1)
void flash_mma() {
    extern __shared__ uint32_t smu[];
    const uint4* KU4 = (const uint4*)smu;
    const uint4* VU4 = (const uint4*)(smu + FSTG * 4096);
    const uint32_t ks_base = smem_u32(smu);
    const uint32_t vs_base = smem_u32(smu + FSTG * 4096);

    const int i0 = (gridDim.x - 1 - blockIdx.x) * 128;  // heavy blocks first
    const int h = blockIdx.y, b = blockIdx.z;
    const int tid = threadIdx.x;
    const int wid = tid >> 5, lane = tid & 31;
    const int qk = lane & 3, qr = lane >> 2;
    const int m0 = wid * 16;

    const int bh = b * Hc + h;
    const float2* kb2 = (const float2*)(g_k + (size_t)bh * Sc * Pc);
    const uint32_t* kfb = g_qvf_u + (size_t)bh * 8 * 4096;
    const uint32_t* vfb = g_vf_u + (size_t)bh * 8 * 4096;
    const float qscale = rsqrtf((float)Ec);

    // Q A-frags (fp16) from raw g_k
    uint32_t qa[4][4];
    {
        const int r0g = i0 + m0 + qr, r1g = r0g + 8;
#pragma unroll
        for (int kg = 0; kg < 4; kg++) {
            int c0 = kg * 16 + 2 * qk;
            float2 x0 = kb2[(size_t)r0g * 32 + (c0 >> 1)];
            float2 x1 = kb2[(size_t)r1g * 32 + (c0 >> 1)];
            float2 x2 = kb2[(size_t)r0g * 32 + ((c0 + 8) >> 1)];
            float2 x3 = kb2[(size_t)r1g * 32 + ((c0 + 8) >> 1)];
            qa[kg][0] = h2u(x0.x * qscale, x0.y * qscale);
            qa[kg][1] = h2u(x1.x * qscale, x1.y * qscale);
            qa[kg][2] = h2u(x2.x * qscale, x2.y * qscale);
            qa[kg][3] = h2u(x3.x * qscale, x3.y * qscale);
        }
    }

    auto fill = [&](int t) {
        const int buf = t % FSTG;
        const uint32_t* ksrc = kfb + (size_t)t * 4096;
        const uint32_t* vsrc = vfb + (size_t)t * 4096;
#pragma unroll
        for (int j = 0; j < 4; j++) {
            int u = (j * 256 + tid) * 4;
            cp_async16(ks_base + (buf * 4096 + u) * 4, ksrc + u);
            cp_async16(vs_base + (buf * 4096 + u) * 4, vsrc + u);
        }
        CP_COMMIT();
    };

    float mrow[2] = {-INFINITY, -INFINITY};
    float lrow[2] = {0.f, 0.f};
    float o[8][4];
#pragma unroll
    for (int nt = 0; nt < 8; nt++)
#pragma unroll
        for (int q = 0; q < 4; q++) o[nt][q] = 0.f;

    const int tN = i0 / 128 + 1;
    fill(0);
    if (tN > 1) fill(1);

    for (int t = 0; t < tN; t++) {
        int issued = (t + 2 < tN) ? (t + 2) : tN;
        cp_wait_n(issued - (t + 1));
        __syncthreads();
        if (t + 2 < tN) fill(t + 2);
        const int kb4 = (t % FSTG) * 1024;

        // S = Q @ K^T
        float s[16][4];
#pragma unroll
        for (int nt = 0; nt < 16; nt++)
#pragma unroll
            for (int q = 0; q < 4; q++) s[nt][q] = 0.f;

#pragma unroll
        for (int kg = 0; kg < 4; kg++) {
#pragma unroll
            for (int fp = 0; fp < 8; fp++) {
                uint4 bb = KU4[kb4 + (kg * 8 + fp) * 32 + lane];
                mma_f16(s[2 * fp], qa[kg], bb.x, bb.y);
                mma_f16(s[2 * fp + 1], qa[kg], bb.z, bb.w);
            }
        }

        if (t == tN - 1) {  // causal mask on diagonal block
            int r0 = m0 + qr, r1 = r0 + 8;
#pragma unroll
            for (int nt = 0; nt < 16; nt++) {
                int c0 = nt * 8 + 2 * qk;
                if (c0 > r0)     s[nt][0] = -INFINITY;
                if (c0 + 1 > r0) s[nt][1] = -INFINITY;
                if (c0 > r1)     s[nt][2] = -INFINITY;
                if (c0 + 1 > r1) s[nt][3] = -INFINITY;
            }
        }

        // online softmax; p packed to fp16 A-frags in registers
        float mx0 = mrow[0], mx1 = mrow[1];
#pragma unroll
        for (int nt = 0; nt < 16; nt++) {
            mx0 = fmaxf(mx0, fmaxf(s[nt][0], s[nt][1]));
            mx1 = fmaxf(mx1, fmaxf(s[nt][2], s[nt][3]));
        }
#pragma unroll
        for (int off = 1; off <= 2; off <<= 1) {
            mx0 = fmaxf(mx0, __shfl_xor_sync(0xffffffffu, mx0, off));
            mx1 = fmaxf(mx1, __shfl_xor_sync(0xffffffffu, mx1, off));
        }
        float alpha0 = __expf(mrow[0] - mx0);
        float alpha1 = __expf(mrow[1] - mx1);
        mrow[0] = mx0; mrow[1] = mx1;
        float sum0 = 0.f, sum1 = 0.f;
        uint32_t plo[16], phi[16];
#pragma unroll
        for (int nt = 0; nt < 16; nt++) {
            float p0 = __expf(s[nt][0] - mx0);
            float p1 = __expf(s[nt][1] - mx0);
            float p2 = __expf(s[nt][2] - mx1);
            float p3 = __expf(s[nt][3] - mx1);
            uint32_t lo = h2u(p0, p1), hi = h2u(p2, p3);
            plo[nt] = lo; phi[nt] = hi;
            float2 lf = __half22float2(*(__half2*)&lo);
            float2 hf = __half22float2(*(__half2*)&hi);
            sum0 += lf.x + lf.y;
            sum1 += hf.x + hf.y;
        }
#pragma unroll
        for (int off = 1; off <= 2; off <<= 1) {
            sum0 += __shfl_xor_sync(0xffffffffu, sum0, off);
            sum1 += __shfl_xor_sync(0xffffffffu, sum1, off);
        }
        lrow[0] = lrow[0] * alpha0 + sum0;
        lrow[1] = lrow[1] * alpha1 + sum1;
#pragma unroll
        for (int nt = 0; nt < 8; nt++) {
            o[nt][0] *= alpha0; o[nt][1] *= alpha0;
            o[nt][2] *= alpha1; o[nt][3] *= alpha1;
        }

        // O += P @ V
#pragma unroll
        for (int kg = 0; kg < 8; kg++) {
            uint32_t a[4] = {plo[2 * kg], phi[2 * kg],
                             plo[2 * kg + 1], phi[2 * kg + 1]};
#pragma unroll
            for (int fp = 0; fp < 4; fp++) {
                uint4 vv = VU4[kb4 + (kg * 4 + fp) * 32 + lane];
                mma_f16(o[2 * fp], a, vv.x, vv.y);
                mma_f16(o[2 * fp + 1], a, vv.z, vv.w);
            }
        }
    }
    __syncthreads();

    // epilogue: O -> fp16 A-frag chunks for lift (staged, coalesced out)
    const float inv0 = 1.f / lrow[0], inv1 = 1.f / lrow[1];
    const int rl0 = m0 + qr;
    __half* hst = (__half*)smu;
#pragma unroll
    for (int nt = 0; nt < 8; nt++) {
        int cc = nt * 8 + 2 * qk;
        int ch0 = (cc >> 5) * 4096, ch1 = ((cc + 1) >> 5) * 4096;
        hst[ch0 + amap(rl0, cc & 31)]           = __float2half_rn(o[nt][0] * inv0);
        hst[ch1 + amap(rl0, (cc + 1) & 31)]     = __float2half_rn(o[nt][1] * inv0);
        hst[ch0 + amap(rl0 + 8, cc & 31)]       = __float2half_rn(o[nt][2] * inv1);
        hst[ch1 + amap(rl0 + 8, (cc + 1) & 31)] = __float2half_rn(o[nt][3] * inv1);
    }
    __syncthreads();
    {
        uint32_t* dst = g_attnf_u +
            (((size_t)(b * 8 + i0 / 128)) * 24 + h * 2) * 2048;
#pragma unroll
        for (int j = 0; j < 4; j++) {
            int u = (j * 256 + tid) * 4;
            *(uint4*)(dst + u) = *(const uint4*)(smu + u);
        }
    }
}

}  // namespace

extern "C" void kernel_launch(void* const* d_in, const int* in_sizes, int n_in,
                              void* d_out, int out_size) {
    (void)in_sizes; (void)n_in; (void)out_size;
    const float* x  = (const float*)d_in[0];   // (B,1,S,E)
    const float* kp = (const float*)d_in[1];   // (H,E,P)
    const float* vp = (const float*)d_in[2];   // (H,E,P)
    const float* qh = (const float*)d_in[3];   // (H,S,S)
    const float* lw = (const float*)d_in[4];   // (1,HP,E)
    float* out = (float*)d_out;                // (B,S,E)

    cudaFuncSetAttribute(mma_gemm<128, 0>,
                         cudaFuncAttributeMaxDynamicSharedMemorySize, SMG128);
    cudaFuncSetAttribute(mma_gemm<64, 1>,
                         cudaFuncAttributeMaxDynamicSharedMemorySize, SMG64);
    cudaFuncSetAttribute(mma_gemm<128, 2>,
                         cudaFuncAttributeMaxDynamicSharedMemorySize, SMG128);
    cudaFuncSetAttribute(flash_mma,
                         cudaFuncAttributeMaxDynamicSharedMemorySize, SMEM_FLASH);

    round_all<<<5040, 256>>>(kp, vp, lw, x, qh);
    mma_gemm<128, 0><<<dim3(Sc / 128, Hc, Bc), 256, SMG128>>>(nullptr);
    mma_gemm<64, 1><<<dim3(Sc / 128, Hc, Bc), 256, SMG64>>>(nullptr);
    flash_mma<<<dim3(Sc / 128, Hc, Bc), 256, SMEM_FLASH>>>();
    mma_gemm<128, 2><<<dim3(Bc * Sc / 128, Ec / 128), 256, SMG128>>>(out);
}

// round 17
// speedup vs baseline: 1.9739x; 1.0193x over previous
#include <cuda_runtime.h>
#include <cuda_fp16.h>
#include <math.h>
#include <stdint.h>

namespace {

constexpr int Bc = 8, Sc = 1024, Ec = 768, Hc = 12, Pc = 64, HPc = 768;

// fp16 scratch (uint32 = half2). Layout docs at each index fn.
__device__ float    g_k[Bc * Hc * Sc * Pc];          // fp32 raw (flash Q src)
__device__ uint32_t g_qvf_u[96 * 8 * 4096];          // flash K tiles (B-frag)
__device__ uint32_t g_vf_u[96 * 8 * 4096];           // flash V tiles (B-frag)
__device__ uint32_t g_vbf_u[96 * 32 * 1024];         // qv B chunks (B-frag, NT64)
__device__ uint32_t g_attnf_u[64 * 24 * 2048];       // lift A chunks (A-frag)
__device__ uint32_t g_wkvf_u[12 * 24 * 2048];        // proj B chunks (B-frag, NT128)
__device__ uint32_t g_lwf_u[6 * 24 * 2048];          // lift B chunks
__device__ uint32_t g_xf_u[64 * 24 * 2048];          // proj A chunks (A-frag)
__device__ uint32_t g_qhf_u[96 * 32 * 2048];         // qv A chunks (A-frag)

__device__ __forceinline__ uint32_t h2u(float lo, float hi) {
    __half2 h = __floats2half2_rn(lo, hi);
    return *(uint32_t*)&h;
}
__device__ __forceinline__ uint32_t ex2_h2(uint32_t x) {
    uint32_t y;
    asm("ex2.approx.f16x2 %0, %1;" : "=r"(y) : "r"(x));
    return y;
}
__device__ __forceinline__ float ex2_f(float x) {
    float y;
    asm("ex2.approx.f32 %0, %1;" : "=f"(y) : "f"(x));
    return y;
}
__device__ __forceinline__ uint32_t hadd2(uint32_t a, uint32_t b) {
    uint32_t c;
    asm("add.f16x2 %0, %1, %2;" : "=r"(c) : "r"(a), "r"(b));
    return c;
}

__device__ __forceinline__ void mma_f16(float c[4], const uint32_t a[4],
                                        uint32_t b0, uint32_t b1) {
    asm volatile(
        "mma.sync.aligned.m16n8k16.row.col.f32.f16.f16.f32 "
        "{%0,%1,%2,%3}, {%4,%5,%6,%7}, {%8,%9}, {%0,%1,%2,%3};"
        : "+f"(c[0]), "+f"(c[1]), "+f"(c[2]), "+f"(c[3])
        : "r"(a[0]), "r"(a[1]), "r"(a[2]), "r"(a[3]), "r"(b0), "r"(b1));
}

__device__ __forceinline__ uint32_t smem_u32(const void* p) {
    uint32_t a;
    asm("{ .reg .u64 t; cvta.to.shared.u64 t, %1; cvt.u32.u64 %0, t; }"
        : "=r"(a) : "l"(p));
    return a;
}
__device__ __forceinline__ void cp_async16(uint32_t dst, const void* src) {
    asm volatile("cp.async.cg.shared.global [%0], [%1], 16;"
                 :: "r"(dst), "l"(src) : "memory");
}
#define CP_COMMIT() asm volatile("cp.async.commit_group;" ::: "memory")
__device__ __forceinline__ void cp_wait_n(int n) {
    if (n <= 0)      asm volatile("cp.async.wait_group 0;" ::: "memory");
    else if (n == 1) asm volatile("cp.async.wait_group 1;" ::: "memory");
    else if (n == 2) asm volatile("cp.async.wait_group 2;" ::: "memory");
    else             asm volatile("cp.async.wait_group 3;" ::: "memory");
}

// ---- half-index maps (value position -> half index within one chunk) ----
template <int NT>
__device__ __forceinline__ int bmap(int k, int n) {
    int kg = k >> 4, kl = k & 15, f = n >> 3, qr = n & 7;
    int u = (kg * (NT / 16) + (f >> 1)) * 128 +
            (qr * 4 + ((kl & 7) >> 1)) * 4 + (f & 1) * 2 + ((kl >> 3) & 1);
    return u * 2 + (kl & 1);
}
__device__ __forceinline__ int amap(int m, int k) {
    int kg = k >> 4, kl = k & 15;
    int u = ((m >> 4) * 2 + kg) * 128 +
            ((m & 7) * 4 + ((kl & 7) >> 1)) * 4 + ((m >> 3) & 1) +
            ((kl >> 3) & 1) * 2;
    return u * 2 + (kl & 1);
}
__device__ __forceinline__ int kmap(int j, int p) {
    int kg = p >> 4, kl = p & 15, f = j >> 3, qr = j & 7;
    int u = (kg * 8 + (f >> 1)) * 128 +
            (qr * 4 + ((kl & 7) >> 1)) * 4 + (f & 1) * 2 + ((kl >> 3) & 1);
    return u * 2 + (kl & 1);
}
__device__ __forceinline__ int vmap(int j, int p) {
    int kg = j >> 4, kl = j & 15, f = p >> 3, qr = p & 7;
    int u = (kg * 4 + (f >> 1)) * 128 +
            (qr * 4 + ((kl & 7) >> 1)) * 4 + (f & 1) * 2 + ((kl >> 3) & 1);
    return u * 2 + (kl & 1);
}

// ---------------------------------------------------------------------------
// Fused prologue: all fp16 frag-order conversions in ONE launch.
// blocks [0,432): weights;  [432,1968): x;  [1968,5040): q_heads.
// ---------------------------------------------------------------------------
__global__ __launch_bounds__(256)
void round_all(const float* __restrict__ kp, const float* __restrict__ vp,
               const float* __restrict__ lw, const float* __restrict__ x,
               const float* __restrict__ qh) {
    __shared__ uint32_t sms[2048];
    __half* hs = (__half*)sms;
    const int bid = blockIdx.x, tid = threadIdx.x;
    uint32_t* dst;
    if (bid < 432) {                       // weights -> B-frag chunks
        const int t = bid % 24, y = bid / 24;
#pragma unroll
        for (int j = 0; j < 16; j++) {
            int i = j * 256 + tid;
            int kk = i >> 7, n = i & 127;
            float val;
            if (y < Hc) {
                int e = t * 32 + kk;
                val = (n < 64) ? kp[((size_t)y * Ec + e) * Pc + n]
                               : vp[((size_t)y * Ec + e) * Pc + (n - 64)];
            } else {
                val = lw[(size_t)(t * 32 + kk) * Ec + (y - Hc) * 128 + n];
            }
            hs[bmap<128>(kk, n)] = __float2half_rn(val);
        }
        dst = (y < Hc) ? g_wkvf_u + ((size_t)y * 24 + t) * 2048
                       : g_lwf_u + ((size_t)(y - Hc) * 24 + t) * 2048;
    } else if (bid < 1968) {               // x -> A-frag chunks
        const int r = bid - 432;
        const int t = r % 24, rb = r / 24;
#pragma unroll
        for (int j = 0; j < 16; j++) {
            int i = j * 256 + tid;
            int m = i >> 5, kl = i & 31;
            float val = x[(size_t)(rb * 128 + m) * Ec + t * 32 + kl];
            hs[amap(m, kl)] = __float2half_rn(val);
        }
        dst = g_xf_u + ((size_t)rb * 24 + t) * 2048;
    } else {                               // q_heads -> A-frag chunks
        const int r = bid - 1968;
        const int t = r % 32, rb = (r / 32) % 8, h = r / 256;
#pragma unroll
        for (int j = 0; j < 16; j++) {
            int i = j * 256 + tid;
            int m = i >> 5, kl = i & 31;
            float val = qh[((size_t)h * Sc + rb * 128 + m) * Sc + t * 32 + kl];
            hs[amap(m, kl)] = __float2half_rn(val);
        }
        dst = g_qhf_u + (((size_t)h * 8 + rb) * 32 + t) * 2048;
    }
    __syncthreads();
#pragma unroll
    for (int j = 0; j < 2; j++) {
        int u = (j * 256 + tid) * 4;
        *(uint4*)(dst + u) = *(const uint4*)(sms + u);
    }
}

// ---------------------------------------------------------------------------
// fp16 mma.sync GEMM, 4-stage cp.async pipeline, k-step 32.
// MODE 0: proj (NT=128)  MODE 1: qv (NT=64)  MODE 2: lift (NT=128)
// ---------------------------------------------------------------------------
constexpr int GSTG = 4;

template <int NT, int MODE>
__global__ __launch_bounds__(256, 2)
void mma_gemm(float* __restrict__ Out) {
    constexpr int MT = (NT == 128) ? 4 : 2;
    constexpr int BCH = NT * 16;                // B chunk u32
    constexpr int NTK = (MODE == 1) ? 32 : 24;

    extern __shared__ uint32_t smu[];
    const uint4* AU4 = (const uint4*)smu;
    const uint4* BU4 = (const uint4*)(smu + GSTG * 2048);
    const uint32_t as_base = smem_u32(smu);
    const uint32_t bs_base = smem_u32(smu + GSTG * 2048);

    const int tid = threadIdx.x;
    const int wid = tid >> 5, lane = tid & 31;
    const int wr = (NT == 128) ? (wid >> 2) : (wid >> 1);
    const int wc = (NT == 128) ? (wid & 3) : (wid & 1);
    const int wm0 = wr * ((NT == 128) ? 64 : 32);
    const int mtile0 = wm0 >> 4;
    const int qk = lane & 3, qr = lane >> 2;
    const int wn0 = wc * 32;

    const int bx = blockIdx.x, hy = blockIdx.y, bz = blockIdx.z;
    const int row0 = bx * 128;
    const int bh = bz * Hc + hy;

    const uint32_t* Agf;
    const uint32_t* Bgf;
    int n0g = 0;
    if (MODE == 0) {
        Agf = g_xf_u + ((size_t)(bz * 8 + bx)) * 24 * 2048;
        Bgf = g_wkvf_u + (size_t)hy * 24 * 2048;
    } else if (MODE == 1) {
        Agf = g_qhf_u + ((size_t)(hy * 8 + bx)) * 32 * 2048;
        Bgf = g_vbf_u + (size_t)bh * 32 * 1024;
    } else {
        Agf = g_attnf_u + (size_t)bx * 24 * 2048;
        Bgf = g_lwf_u + (size_t)blockIdx.y * 24 * 2048;
        n0g = blockIdx.y * 128;
    }

    float c[MT][4][4];
#pragma unroll
    for (int mt = 0; mt < MT; mt++)
#pragma unroll
        for (int nt = 0; nt < 4; nt++)
#pragma unroll
            for (int q = 0; q < 4; q++) c[mt][nt][q] = 0.f;

    auto fill = [&](int t) {
        const int buf = t % GSTG;
        const uint32_t* asrc = Agf + (size_t)t * 2048;
#pragma unroll
        for (int j = 0; j < 2; j++) {
            int u = (j * 256 + tid) * 4;
            cp_async16(as_base + (buf * 2048 + u) * 4, asrc + u);
        }
        const uint32_t* bsrc = Bgf + (size_t)t * BCH;
#pragma unroll
        for (int j = 0; j < BCH / 1024; j++) {
            int u = (j * 256 + tid) * 4;
            cp_async16(bs_base + (buf * BCH + u) * 4, bsrc + u);
        }
        CP_COMMIT();
    };

#pragma unroll
    for (int s = 0; s < GSTG - 1; s++)
        if (s < NTK) fill(s);

    for (int t = 0; t < NTK; t++) {
        int issued = (t + GSTG - 1 < NTK) ? (t + GSTG - 1) : NTK;
        cp_wait_n(issued - (t + 1));
        __syncthreads();
        if (t + GSTG - 1 < NTK) fill(t + GSTG - 1);

        const int a4 = (t % GSTG) * 512, b4 = (t % GSTG) * (BCH / 4);
#pragma unroll
        for (int kg = 0; kg < 2; kg++) {
            uint32_t a[MT][4];
#pragma unroll
            for (int mt = 0; mt < MT; mt++) {
                uint4 av = AU4[a4 + ((mtile0 + mt) * 2 + kg) * 32 + lane];
                a[mt][0] = av.x; a[mt][1] = av.y; a[mt][2] = av.z; a[mt][3] = av.w;
            }
#pragma unroll
            for (int j = 0; j < 2; j++) {
                uint4 bb = BU4[b4 + (kg * (NT / 16) + wc * 2 + j) * 32 + lane];
#pragma unroll
                for (int mt = 0; mt < MT; mt++) {
                    mma_f16(c[mt][2 * j], a[mt], bb.x, bb.y);
                    mma_f16(c[mt][2 * j + 1], a[mt], bb.z, bb.w);
                }
            }
        }
    }
    __syncthreads();

    // ---- epilogue ----
    __half* hst = (__half*)smu;
#pragma unroll
    for (int mt = 0; mt < MT; mt++) {
#pragma unroll
        for (int nt = 0; nt < 4; nt++) {
            int rl = wm0 + mt * 16 + qr;
            int col = wn0 + nt * 8 + 2 * qk;
            float v00 = c[mt][nt][0], v01 = c[mt][nt][1];
            float v10 = c[mt][nt][2], v11 = c[mt][nt][3];
            if (MODE == 0) {
                if (col < 64) {
                    size_t off = (size_t)bh * Sc * Pc;
                    *(float2*)(g_k + off + (size_t)(row0 + rl) * Pc + col) =
                        make_float2(v00, v01);
                    *(float2*)(g_k + off + (size_t)(row0 + rl + 8) * Pc + col) =
                        make_float2(v10, v11);
                } else {
                    int cc = col - 64;
                    __half h00 = __float2half_rn(v00), h01 = __float2half_rn(v01);
                    __half h10 = __float2half_rn(v10), h11 = __float2half_rn(v11);
                    hst[vmap(rl, cc)]         = h00;
                    hst[vmap(rl, cc + 1)]     = h01;
                    hst[vmap(rl + 8, cc)]     = h10;
                    hst[vmap(rl + 8, cc + 1)] = h11;
                    int base0 = (4096 + (rl >> 5) * 1024) * 2;
                    int base1 = (4096 + ((rl + 8) >> 5) * 1024) * 2;
                    hst[base0 + bmap<64>(rl & 31, cc)]           = h00;
                    hst[base0 + bmap<64>(rl & 31, cc + 1)]       = h01;
                    hst[base1 + bmap<64>((rl + 8) & 31, cc)]     = h10;
                    hst[base1 + bmap<64>((rl + 8) & 31, cc + 1)] = h11;
                }
            } else if (MODE == 1) {
                hst[kmap(rl, col)]         = __float2half_rn(v00);
                hst[kmap(rl, col + 1)]     = __float2half_rn(v01);
                hst[kmap(rl + 8, col)]     = __float2half_rn(v10);
                hst[kmap(rl + 8, col + 1)] = __float2half_rn(v11);
            } else {
                int row = row0 + rl;
                *(float2*)(Out + (size_t)row * Ec + n0g + col) =
                    make_float2(v00, v01);
                *(float2*)(Out + (size_t)(row + 8) * Ec + n0g + col) =
                    make_float2(v10, v11);
            }
        }
    }
    if (MODE == 0) {
        __syncthreads();
        uint32_t* d1 = g_vf_u + ((size_t)bh * 8 + bx) * 4096;
        uint32_t* d2 = g_vbf_u + (size_t)bh * 32 * 1024 + (size_t)bx * 4096;
#pragma unroll
        for (int j = 0; j < 4; j++) {
            int u = (j * 256 + tid) * 4;
            *(uint4*)(d1 + u) = *(const uint4*)(smu + u);
            *(uint4*)(d2 + u) = *(const uint4*)(smu + 4096 + u);
        }
    } else if (MODE == 1) {
        __syncthreads();
        uint32_t* d1 = g_qvf_u + ((size_t)bh * 8 + bx) * 4096;
#pragma unroll
        for (int j = 0; j < 4; j++) {
            int u = (j * 256 + tid) * 4;
            *(uint4*)(d1 + u) = *(const uint4*)(smu + u);
        }
    }
}

constexpr int SMG128 = GSTG * (2048 + 2048) * 4;   // 96 KB
constexpr int SMG64  = GSTG * (2048 + 1024) * 4;   // 48 KB

// ---------------------------------------------------------------------------
// Flash attention, fp16 mma, log2-domain softmax (ex2.approx.f16x2), P in
// registers, 3-stage K/V pipeline, one barrier per tile.
// Smem: K[3][4096 u32] + V[3][4096 u32] = 96 KB.
// ---------------------------------------------------------------------------
constexpr int FSTG = 3;
constexpr int SMEM_FLASH = 2 * FSTG * 4096 * 4;

__global__ __launch_bounds__(256, 1)
void flash_mma() {
    extern __shared__ uint32_t smu[];
    const uint4* KU4 = (const uint4*)smu;
    const uint4* VU4 = (const uint4*)(smu + FSTG * 4096);
    const uint32_t ks_base = smem_u32(smu);
    const uint32_t vs_base = smem_u32(smu + FSTG * 4096);

    const int i0 = (gridDim.x - 1 - blockIdx.x) * 128;  // heavy blocks first
    const int h = blockIdx.y, b = blockIdx.z;
    const int tid = threadIdx.x;
    const int wid = tid >> 5, lane = tid & 31;
    const int qk = lane & 3, qr = lane >> 2;
    const int m0 = wid * 16;

    const int bh = b * Hc + h;
    const float2* kb2 = (const float2*)(g_k + (size_t)bh * Sc * Pc);
    const uint32_t* kfb = g_qvf_u + (size_t)bh * 8 * 4096;
    const uint32_t* vfb = g_vf_u + (size_t)bh * 8 * 4096;
    // log2e folded into Q scale: softmax runs in the log2 domain
    const float qscale = rsqrtf((float)Ec) * 1.44269504f;

    // Q A-frags (fp16) from raw g_k
    uint32_t qa[4][4];
    {
        const int r0g = i0 + m0 + qr, r1g = r0g + 8;
#pragma unroll
        for (int kg = 0; kg < 4; kg++) {
            int c0 = kg * 16 + 2 * qk;
            float2 x0 = kb2[(size_t)r0g * 32 + (c0 >> 1)];
            float2 x1 = kb2[(size_t)r1g * 32 + (c0 >> 1)];
            float2 x2 = kb2[(size_t)r0g * 32 + ((c0 + 8) >> 1)];
            float2 x3 = kb2[(size_t)r1g * 32 + ((c0 + 8) >> 1)];
            qa[kg][0] = h2u(x0.x * qscale, x0.y * qscale);
            qa[kg][1] = h2u(x1.x * qscale, x1.y * qscale);
            qa[kg][2] = h2u(x2.x * qscale, x2.y * qscale);
            qa[kg][3] = h2u(x3.x * qscale, x3.y * qscale);
        }
    }

    auto fill = [&](int t) {
        const int buf = t % FSTG;
        const uint32_t* ksrc = kfb + (size_t)t * 4096;
        const uint32_t* vsrc = vfb + (size_t)t * 4096;
#pragma unroll
        for (int j = 0; j < 4; j++) {
            int u = (j * 256 + tid) * 4;
            cp_async16(ks_base + (buf * 4096 + u) * 4, ksrc + u);
            cp_async16(vs_base + (buf * 4096 + u) * 4, vsrc + u);
        }
        CP_COMMIT();
    };

    float mrow[2] = {-INFINITY, -INFINITY};
    float lrow[2] = {0.f, 0.f};
    float o[8][4];
#pragma unroll
    for (int nt = 0; nt < 8; nt++)
#pragma unroll
        for (int q = 0; q < 4; q++) o[nt][q] = 0.f;

    const int tN = i0 / 128 + 1;
    fill(0);
    if (tN > 1) fill(1);

    for (int t = 0; t < tN; t++) {
        int issued = (t + 2 < tN) ? (t + 2) : tN;
        cp_wait_n(issued - (t + 1));
        __syncthreads();
        if (t + 2 < tN) fill(t + 2);
        const int kb4 = (t % FSTG) * 1024;

        // S = Q @ K^T (log2-scaled)
        float s[16][4];
#pragma unroll
        for (int nt = 0; nt < 16; nt++)
#pragma unroll
            for (int q = 0; q < 4; q++) s[nt][q] = 0.f;

#pragma unroll
        for (int kg = 0; kg < 4; kg++) {
#pragma unroll
            for (int fp = 0; fp < 8; fp++) {
                uint4 bb = KU4[kb4 + (kg * 8 + fp) * 32 + lane];
                mma_f16(s[2 * fp], qa[kg], bb.x, bb.y);
                mma_f16(s[2 * fp + 1], qa[kg], bb.z, bb.w);
            }
        }

        if (t == tN - 1) {  // causal mask on diagonal block (local indices)
            int r0 = m0 + qr, r1 = r0 + 8;
#pragma unroll
            for (int nt = 0; nt < 16; nt++) {
                int c0 = nt * 8 + 2 * qk;
                if (c0 > r0)     s[nt][0] = -INFINITY;
                if (c0 + 1 > r0) s[nt][1] = -INFINITY;
                if (c0 > r1)     s[nt][2] = -INFINITY;
                if (c0 + 1 > r1) s[nt][3] = -INFINITY;
            }
        }

        // online softmax, log2 domain: p = 2^(s - mx) via ex2.approx.f16x2,
        // result IS the fp16 A-frag for PV.
        float mx0 = mrow[0], mx1 = mrow[1];
#pragma unroll
        for (int nt = 0; nt < 16; nt++) {
            mx0 = fmaxf(mx0, fmaxf(s[nt][0], s[nt][1]));
            mx1 = fmaxf(mx1, fmaxf(s[nt][2], s[nt][3]));
        }
#pragma unroll
        for (int off = 1; off <= 2; off <<= 1) {
            mx0 = fmaxf(mx0, __shfl_xor_sync(0xffffffffu, mx0, off));
            mx1 = fmaxf(mx1, __shfl_xor_sync(0xffffffffu, mx1, off));
        }
        float alpha0 = ex2_f(mrow[0] - mx0);
        float alpha1 = ex2_f(mrow[1] - mx1);
        mrow[0] = mx0; mrow[1] = mx1;

        uint32_t plo[16], phi[16];
#pragma unroll
        for (int nt = 0; nt < 16; nt++) {
            plo[nt] = ex2_h2(h2u(s[nt][0] - mx0, s[nt][1] - mx0));
            phi[nt] = ex2_h2(h2u(s[nt][2] - mx1, s[nt][3] - mx1));
        }
        // sums: one HADD2 level (fp16), then fp32
        float sum0 = 0.f, sum1 = 0.f;
#pragma unroll
        for (int i = 0; i < 16; i += 2) {
            uint32_t pl = hadd2(plo[i], plo[i + 1]);
            uint32_t ph = hadd2(phi[i], phi[i + 1]);
            float2 lf = __half22float2(*(__half2*)&pl);
            float2 hf = __half22float2(*(__half2*)&ph);
            sum0 += lf.x + lf.y;
            sum1 += hf.x + hf.y;
        }
#pragma unroll
        for (int off = 1; off <= 2; off <<= 1) {
            sum0 += __shfl_xor_sync(0xffffffffu, sum0, off);
            sum1 += __shfl_xor_sync(0xffffffffu, sum1, off);
        }
        lrow[0] = lrow[0] * alpha0 + sum0;
        lrow[1] = lrow[1] * alpha1 + sum1;
#pragma unroll
        for (int nt = 0; nt < 8; nt++) {
            o[nt][0] *= alpha0; o[nt][1] *= alpha0;
            o[nt][2] *= alpha1; o[nt][3] *= alpha1;
        }

        // O += P @ V
#pragma unroll
        for (int kg = 0; kg < 8; kg++) {
            uint32_t a[4] = {plo[2 * kg], phi[2 * kg],
                             plo[2 * kg + 1], phi[2 * kg + 1]};
#pragma unroll
            for (int fp = 0; fp < 4; fp++) {
                uint4 vv = VU4[kb4 + (kg * 4 + fp) * 32 + lane];
                mma_f16(o[2 * fp], a, vv.x, vv.y);
                mma_f16(o[2 * fp + 1], a, vv.z, vv.w);
            }
        }
    }
    __syncthreads();

    // epilogue: O -> fp16 A-frag chunks for lift (staged, coalesced out)
    const float inv0 = 1.f / lrow[0], inv1 = 1.f / lrow[1];
    const int rl0 = m0 + qr;
    __half* hst = (__half*)smu;
#pragma unroll
    for (int nt = 0; nt < 8; nt++) {
        int cc = nt * 8 + 2 * qk;
        int ch0 = (cc >> 5) * 4096, ch1 = ((cc + 1) >> 5) * 4096;
        hst[ch0 + amap(rl0, cc & 31)]           = __float2half_rn(o[nt][0] * inv0);
        hst[ch1 + amap(rl0, (cc + 1) & 31)]     = __float2half_rn(o[nt][1] * inv0);
        hst[ch0 + amap(rl0 + 8, cc & 31)]       = __float2half_rn(o[nt][2] * inv1);
        hst[ch1 + amap(rl0 + 8, (cc + 1) & 31)] = __float2half_rn(o[nt][3] * inv1);
    }
    __syncthreads();
    {
        uint32_t* dst = g_attnf_u +
            (((size_t)(b * 8 + i0 / 128)) * 24 + h * 2) * 2048;
#pragma unroll
        for (int j = 0; j < 4; j++) {
            int u = (j * 256 + tid) * 4;
            *(uint4*)(dst + u) = *(const uint4*)(smu + u);
        }
    }
}

}  // namespace

extern "C" void kernel_launch(void* const* d_in, const int* in_sizes, int n_in,
                              void* d_out, int out_size) {
    (void)in_sizes; (void)n_in; (void)out_size;
    const float* x  = (const float*)d_in[0];   // (B,1,S,E)
    const float* kp = (const float*)d_in[1];   // (H,E,P)
    const float* vp = (const float*)d_in[2];   // (H,E,P)
    const float* qh = (const float*)d_in[3];   // (H,S,S)
    const float* lw = (const float*)d_in[4];   // (1,HP,E)
    float* out = (float*)d_out;                // (B,S,E)

    cudaFuncSetAttribute(mma_gemm<128, 0>,
                         cudaFuncAttributeMaxDynamicSharedMemorySize, SMG128);
    cudaFuncSetAttribute(mma_gemm<64, 1>,
                         cudaFuncAttributeMaxDynamicSharedMemorySize, SMG64);
    cudaFuncSetAttribute(mma_gemm<128, 2>,
                         cudaFuncAttributeMaxDynamicSharedMemorySize, SMG128);
    cudaFuncSetAttribute(flash_mma,
                         cudaFuncAttributeMaxDynamicSharedMemorySize, SMEM_FLASH);

    round_all<<<5040, 256>>>(kp, vp, lw, x, qh);
    mma_gemm<128, 0><<<dim3(Sc / 128, Hc, Bc), 256, SMG128>>>(nullptr);
    mma_gemm<64, 1><<<dim3(Sc / 128, Hc, Bc), 256, SMG64>>>(nullptr);
    flash_mma<<<dim3(Sc / 128, Hc, Bc), 256, SMEM_FLASH>>>();
    mma_gemm<128, 2><<<dim3(Bc * Sc / 128, Ec / 128), 256, SMG128>>>(out);
}